// round 11
// baseline (speedup 1.0000x reference)
#include <cuda_runtime.h>
#include <cuda_fp16.h>
#include <cuda_fp8.h>
#include <math.h>

#define B_DIM 32
#define S_DIM 325
#define L_DIM 192
#define NSEQ (B_DIM * S_DIM)   // 10400
#define DH 128
#define NH 8
#define NEG_F (-1000000000.0f)

// ---- qk fp8 MMA kernel geometry ----
#define MSEQ 32                          // sequences per block (exact: 325*32 = 10400)
#define WB 160                           // byte stride: 128 data + 32 ext (x/bias fold)
#define NBLK (NSEQ / MSEQ)               // 325
#define SM_W  (512 * WB)                 // 81920
#define SM_HA SM_W                       // h buffer 0: [32][WB] fp8 (+ext cols)
#define SM_HB (SM_W + MSEQ * WB)         // h buffer 1
#define QK_SMEM (SM_W + 2 * MSEQ * WB)   // 92160 bytes -> 2 blocks/SM

#define ATTN_SMEM ((32*129 + 32*336 + 32*193) * 4) // 84224 bytes

// ---- scratch (static device arrays; no allocation allowed) ----
__device__ float g_xT[L_DIM * NSEQ];            // x transposed [t][n]
__device__ float g_q[NH * NSEQ * DH];           // [h][n][d]
__device__ float g_k[NH * NSEQ * DH];           // [h][n][d]
__device__ float g_v[NH * NSEQ * L_DIM];        // [h][n][l]

__device__ __forceinline__ float sigf(float x) { return 1.0f / (1.0f + __expf(-x)); }
__device__ __forceinline__ float tanh_fast(float x) { return 2.0f / (1.0f + __expf(-2.0f * x)) - 1.0f; }

__device__ __forceinline__ __half2 tanh2(__half2 x) {
    unsigned y, xi = *(unsigned*)&x;
    asm("tanh.approx.f16x2 %0, %1;" : "=r"(y) : "r"(xi));
    return *(__half2*)&y;
}
__device__ __forceinline__ unsigned short f32x2_to_e4m3x2(float lo, float hi) {
    unsigned short r;
    asm("cvt.rn.satfinite.e4m3x2.f32 %0, %1, %2;" : "=h"(r) : "f"(hi), "f"(lo));
    return r;
}
__device__ __forceinline__ unsigned short h2_to_e4m3x2(__half2 v) {
    unsigned short r;
    unsigned vi = *(unsigned*)&v;
    asm("cvt.rn.satfinite.e4m3x2.f16x2 %0, %1;" : "=h"(r) : "r"(vi));
    return r;
}
__device__ __forceinline__ unsigned char e4m3b(float v) {
    __nv_fp8_e4m3 f(v);
    return *(unsigned char*)&f;
}
__device__ __forceinline__ float e4m3f(unsigned char b) {
    return float(*(__nv_fp8_e4m3*)&b);
}

__device__ __forceinline__ void ldsm4(unsigned& r0, unsigned& r1, unsigned& r2, unsigned& r3,
                                      const void* p) {
    unsigned a = (unsigned)__cvta_generic_to_shared(p);
    asm volatile("ldmatrix.sync.aligned.m8n8.x4.shared.b16 {%0,%1,%2,%3}, [%4];"
                 : "=r"(r0), "=r"(r1), "=r"(r2), "=r"(r3) : "r"(a));
}
__device__ __forceinline__ void mma_fp8(float* d, const unsigned* a, unsigned b0, unsigned b1) {
    asm volatile("mma.sync.aligned.m16n8k32.row.col.f32.e4m3.e4m3.f32 "
                 "{%0,%1,%2,%3}, {%4,%5,%6,%7}, {%8,%9}, {%0,%1,%2,%3};"
                 : "+f"(d[0]), "+f"(d[1]), "+f"(d[2]), "+f"(d[3])
                 : "r"(a[0]), "r"(a[1]), "r"(a[2]), "r"(a[3]), "r"(b0), "r"(b1));
}

// ---------------- dummy (shifts ncu capture slot onto qk kernel) ----------------
__global__ void dummy_kernel() {}

// ---------------- x transpose: [n][t] -> [t][n] ----------------
__global__ void xT_kernel(const float* __restrict__ x) {
    int i = blockIdx.x * 256 + threadIdx.x;
    if (i < NSEQ * L_DIM) {
        int n = i / L_DIM, t = i - n * L_DIM;
        g_xT[t * NSEQ + n] = x[i];
    }
}

// ---------------- v LSTM (hidden size 1) ----------------
__global__ void v_lstm_kernel(const float* __restrict__ Wih, const float* __restrict__ Whh,
                              const float* __restrict__ bih, const float* __restrict__ bhh) {
    int n = blockIdx.x * 256 + threadIdx.x;
    int h = blockIdx.y;
    if (n >= NSEQ) return;
    float wi[4], wh[4], bb[4];
#pragma unroll
    for (int g = 0; g < 4; g++) {
        wi[g] = Wih[h * 4 + g];
        wh[g] = Whh[h * 4 + g];
        bb[g] = bih[h * 4 + g] + bhh[h * 4 + g];
    }
    float hv = 0.f, c = 0.f;
    float4 buf;
    float* vout = g_v + ((size_t)h * NSEQ + n) * L_DIM;
    for (int t = 0; t < L_DIM; t++) {
        float xv = g_xT[t * NSEQ + n];
        float zi = xv * wi[0] + hv * wh[0] + bb[0];
        float zf = xv * wi[1] + hv * wh[1] + bb[1];
        float zg = xv * wi[2] + hv * wh[2] + bb[2];
        float zo = xv * wi[3] + hv * wh[3] + bb[3];
        c = sigf(zf) * c + sigf(zi) * tanh_fast(zg);
        hv = sigf(zo) * tanh_fast(c);
        ((float*)&buf)[t & 3] = hv;
        if ((t & 3) == 3) *(float4*)(vout + (t - 3)) = buf;
    }
}

// ---------------- q/k LSTM on fp8 tensor cores (m16n8k32 e4m3) ----------------
// grid (325, 16), 256 threads = 8 warps, 2 blocks/SM. K extended by one 32-wide
// chunk: A-ext = [x_t, 1, 1, 1], W-ext = [Wih, b_hi, b_lo, b_lo2] so the MMA
// emits the complete pre-activation z. No per-thread Wih/bias registers.
__global__ __launch_bounds__(256, 2) void qk_lstm_fp8(
    const float* __restrict__ qWih, const float* __restrict__ qWhh,
    const float* __restrict__ qbih, const float* __restrict__ qbhh,
    const float* __restrict__ kWih, const float* __restrict__ kWhh,
    const float* __restrict__ kbih, const float* __restrict__ kbhh) {
    extern __shared__ char sm[];
    unsigned char* ws = (unsigned char*)sm;          // permuted Whh e4m3 [512][WB]
    unsigned char* hbufA = (unsigned char*)(sm + SM_HA);
    unsigned char* hbufB = (unsigned char*)(sm + SM_HB);

    const int tid = threadIdx.x;
    const int warp = tid >> 5, lane = tid & 31;
    const int wv = warp;
    const int q4 = lane >> 2, r4 = lane & 3;
    const int grp = lane >> 3, ro = lane & 7;
    const int p = blockIdx.y, head = p & 7;
    const bool is_q = p < 8;
    const int n0 = blockIdx.x * MSEQ;

    const float* Wih = (is_q ? qWih : kWih) + head * 512;
    const float* Whh = (is_q ? qWhh : kWhh) + (size_t)head * 512 * 128;
    const float* bih = (is_q ? qbih : kbih) + head * 512;
    const float* bhh = (is_q ? qbhh : kbhh) + head * 512;

    // zero everything (ws ext tail bytes + h buffers must be 0)
    for (int i = tid; i < QK_SMEM / 4; i += 256) ((unsigned*)sm)[i] = 0u;
    __syncthreads();

    // stage permuted recurrent weights as e4m3
    for (int i = tid; i < 512 * 64; i += 256) {
        int row = i >> 6, kp = i & 63;
        int g = row >> 7, j = row & 127;
        int pcol = (j >> 4) * 64 + (g * 2 + ((j >> 3) & 1)) * 8 + (j & 7);
        float w0 = Whh[row * 128 + 2 * kp];
        float w1 = Whh[row * 128 + 2 * kp + 1];
        *(unsigned short*)(ws + pcol * WB + 2 * kp) = f32x2_to_e4m3x2(w0, w1);
    }
    // stage ext columns: [Wih, b_hi, b_lo, b_lo2] per permuted column
    for (int row = tid; row < 512; row += 256) {
        int g = row >> 7, j = row & 127;
        int pcol = (j >> 4) * 64 + (g * 2 + ((j >> 3) & 1)) * 8 + (j & 7);
        float b = bih[row] + bhh[row];
        unsigned char wx = e4m3b(Wih[row]);
        unsigned char bh = e4m3b(b);
        float r1 = b - e4m3f(bh);
        unsigned char bl = e4m3b(r1);
        unsigned char bl2 = e4m3b(r1 - e4m3f(bl));
        *(unsigned*)(ws + pcol * WB + 128) =
            (unsigned)wx | ((unsigned)bh << 8) | ((unsigned)bl << 16) | ((unsigned)bl2 << 24);
    }
    // h buffer 0 ext: [x_0, 1, 1, 1] per row (e4m3 1.0 = 0x38)
    if (tid < 32) {
        unsigned short xw = f32x2_to_e4m3x2(g_xT[n0 + tid], 0.f);
        *(unsigned*)(hbufA + tid * WB + 128) = 0x38383800u | (unsigned)(xw & 0xFF);
    }

    __half2 c2[2][2][2];
#pragma unroll
    for (int m = 0; m < 2; m++)
#pragma unroll
        for (int uh = 0; uh < 2; uh++)
#pragma unroll
            for (int pr = 0; pr < 2; pr++) c2[m][uh][pr] = __floats2half2_rn(0.f, 0.f);

    // ldmatrix lane address components (byte offsets, fp8: 16B k-halves)
    const int a_row = (grp & 1) * 8 + ro, a_kB = (grp >> 1) * 16;
    const int b_row = (grp >> 1) * 8 + ro, b_kB = (grp & 1) * 16;
    const int wN0 = wv * 64;
    const __half2 H05 = __floats2half2_rn(0.5f, 0.5f);

    // rolling x prefetch register (warp 0 only): holds x_{t+1} during step t
    float xnext = 0.f;
    if (warp == 0) xnext = g_xT[NSEQ + n0 + lane];  // x_1

    __syncthreads();

    for (int t = 0; t < L_DIM; t++) {
        const unsigned char* hc = (t & 1) ? hbufB : hbufA;
        unsigned char* hn = (t & 1) ? hbufA : hbufB;

        float acc[2][8][4];
#pragma unroll
        for (int m = 0; m < 2; m++)
#pragma unroll
            for (int j = 0; j < 8; j++)
#pragma unroll
                for (int e = 0; e < 4; e++) acc[m][j][e] = 0.f;

        // Z = [H | x 1 1 1] @ [W | Wih b]^T over K=160 in 5 k32 chunks
#pragma unroll
        for (int kc = 0; kc < 5; kc++) {
            const int koff = kc * 32;
            unsigned a[2][4], b[4][4];
#pragma unroll
            for (int m = 0; m < 2; m++)
                ldsm4(a[m][0], a[m][1], a[m][2], a[m][3],
                      hc + (m * 16 + a_row) * WB + koff + a_kB);
#pragma unroll
            for (int jj = 0; jj < 4; jj++)
                ldsm4(b[jj][0], b[jj][1], b[jj][2], b[jj][3],
                      ws + (wN0 + jj * 16 + b_row) * WB + koff + b_kB);
#pragma unroll
            for (int m = 0; m < 2; m++)
#pragma unroll
                for (int jj = 0; jj < 4; jj++) {
                    mma_fp8(acc[m][2 * jj],     a[m], b[jj][0], b[jj][1]);
                    mma_fp8(acc[m][2 * jj + 1], a[m], b[jj][2], b[jj][3]);
                }
        }

        // epilogue: acc IS z. LSTM nonlinearity (f16x2), h -> fp8 SMEM
#pragma unroll
        for (int m = 0; m < 2; m++)
#pragma unroll
            for (int pr = 0; pr < 2; pr++) {
                const int rl = m * 16 + q4 + pr * 8;   // row (seq) in block
                const int e = 2 * pr;
#pragma unroll
                for (int uh = 0; uh < 2; uh++) {
                    __half2 zi = __floats2half2_rn(acc[m][0 + uh][e], acc[m][0 + uh][e + 1]);
                    __half2 zf = __floats2half2_rn(acc[m][2 + uh][e], acc[m][2 + uh][e + 1]);
                    __half2 zg = __floats2half2_rn(acc[m][4 + uh][e], acc[m][4 + uh][e + 1]);
                    __half2 zo = __floats2half2_rn(acc[m][6 + uh][e], acc[m][6 + uh][e + 1]);
                    __half2 si = __hfma2(tanh2(__hmul2(zi, H05)), H05, H05);
                    __half2 sf = __hfma2(tanh2(__hmul2(zf, H05)), H05, H05);
                    __half2 so = __hfma2(tanh2(__hmul2(zo, H05)), H05, H05);
                    __half2 tg = tanh2(zg);
                    __half2 cc = __hfma2(sf, c2[m][uh][pr], __hmul2(si, tg));
                    c2[m][uh][pr] = cc;
                    __half2 h2 = __hmul2(so, tanh2(cc));
                    const int u0 = 16 * wv + uh * 8 + 2 * r4;
                    *(unsigned short*)(hn + rl * WB + u0) = h2_to_e4m3x2(h2);
                    if (t == L_DIM - 1) {
                        float* ob = (is_q ? g_q : g_k) + (size_t)head * NSEQ * DH;
                        float2 f = __half22float2(h2);
                        ob[(size_t)(n0 + rl) * DH + u0]     = f.x;
                        ob[(size_t)(n0 + rl) * DH + u0 + 1] = f.y;
                    }
                }
            }

        // ext word for t+1 (warp 0): [x_{t+1}, 1, 1, 1]; then prefetch x_{t+2}
        if (warp == 0 && t < L_DIM - 1) {
            unsigned short xw = f32x2_to_e4m3x2(xnext, 0.f);
            *(unsigned*)(hn + lane * WB + 128) = 0x38383800u | (unsigned)(xw & 0xFF);
            if (t + 2 < L_DIM) xnext = g_xT[(t + 2) * NSEQ + n0 + lane];
        }
        __syncthreads();
    }
}

// ---------------- attention: scores + leaky + mask + softmax + AV + leaky ----------------
__global__ __launch_bounds__(256, 2) void attn_kernel(const float* __restrict__ graph,
                                                      float* __restrict__ out) {
    extern __shared__ char smem_raw[];
    float* qs = (float*)smem_raw;     // [32][129]
    float* sc = qs + 32 * 129;        // [32][336]
    float* kv = sc + 32 * 336;        // [32][193]

    const int tid = threadIdx.x;
    const int h = blockIdx.z, b = blockIdx.y;
    const int s0 = blockIdx.x * 32;
    const int nrows = min(32, S_DIM - s0);
    const int w = tid >> 5, lane = tid & 31;

    for (int i = tid; i < nrows * 128; i += 256) {
        int r = i >> 7, d = i & 127;
        qs[r * 129 + d] = g_q[((size_t)h * NSEQ + (size_t)b * S_DIM + s0 + r) * 128 + d];
    }
    __syncthreads();

    for (int tk = 0; tk < S_DIM; tk += 32) {
        int tw = min(32, S_DIM - tk);
        for (int i = tid; i < tw * 128; i += 256) {
            int r = i >> 7, d = i & 127;
            kv[r * 129 + d] = g_k[((size_t)h * NSEQ + (size_t)b * S_DIM + tk + r) * 128 + d];
        }
        __syncthreads();
        int si = lane;
        int tl0 = w * 4;
        if (si < nrows && tl0 < tw) {
            float a0 = 0, a1 = 0, a2 = 0, a3 = 0;
            const float* qrow = qs + si * 129;
            const float* k0 = kv + tl0 * 129;
#pragma unroll 4
            for (int d = 0; d < 128; d++) {
                float qv = qrow[d];
                a0 = fmaf(qv, k0[d], a0);
                a1 = fmaf(qv, k0[129 + d], a1);
                a2 = fmaf(qv, k0[258 + d], a2);
                a3 = fmaf(qv, k0[387 + d], a3);
            }
            float av[4] = {a0, a1, a2, a3};
#pragma unroll
            for (int j = 0; j < 4; j++) {
                int t = tk + tl0 + j;
                if (t < S_DIM) {
                    float v = av[j] * 0.08838834764831845f;  // 1/sqrt(128)
                    v = (v >= 0.f) ? v : 0.2f * v;           // leaky
                    float gval = graph[(size_t)t * S_DIM + (s0 + si)];
                    if (s0 + si == t) gval += 1.f;
                    if (gval == 0.f) v += NEG_F;             // mask
                    sc[si * 336 + t] = v;
                }
            }
        }
        __syncthreads();
    }

    for (int si = w; si < nrows; si += 8) {
        float* row = sc + si * 336;
        float m = -3.0e38f;
        for (int j = lane; j < S_DIM; j += 32) m = fmaxf(m, row[j]);
#pragma unroll
        for (int o = 16; o; o >>= 1) m = fmaxf(m, __shfl_xor_sync(0xffffffffu, m, o));
        float ssum = 0.f;
        for (int j = lane; j < S_DIM; j += 32) {
            float e = __expf(row[j] - m);
            row[j] = e;
            ssum += e;
        }
#pragma unroll
        for (int o = 16; o; o >>= 1) ssum += __shfl_xor_sync(0xffffffffu, ssum, o);
        float inv = 1.0f / ssum;
        for (int j = lane; j < S_DIM; j += 32) row[j] *= inv;
    }
    __syncthreads();

    float acc[24];
#pragma unroll
    for (int j = 0; j < 24; j++) acc[j] = 0.f;
    const int si2 = tid >> 3;
    const int lq = tid & 7;
    for (int tk = 0; tk < S_DIM; tk += 32) {
        int tw = min(32, S_DIM - tk);
        for (int i = tid; i < tw * 192; i += 256) {
            int r = i / 192, l = i - r * 192;
            kv[r * 193 + l] = g_v[((size_t)h * NSEQ + (size_t)b * S_DIM + tk + r) * 192 + l];
        }
        __syncthreads();
        if (si2 < nrows) {
            for (int t = 0; t < tw; t++) {
                float a = sc[si2 * 336 + tk + t];
                const float* vrow = kv + t * 193 + lq;
#pragma unroll
                for (int j = 0; j < 24; j++) acc[j] = fmaf(a, vrow[8 * j], acc[j]);
            }
        }
        __syncthreads();
    }
    if (si2 < nrows) {
        size_t base = ((size_t)(b * S_DIM + s0 + si2) * 192) * 8 + h;
#pragma unroll
        for (int j = 0; j < 24; j++) {
            float v = acc[j];
            v = (v >= 0.f) ? v : 0.2f * v;  // final leaky
            out[base + (size_t)(lq + 8 * j) * 8] = v;
        }
    }
}

extern "C" void kernel_launch(void* const* d_in, const int* in_sizes, int n_in,
                              void* d_out, int out_size) {
    const float* x     = (const float*)d_in[0];
    const float* graph = (const float*)d_in[1];
    const float* qWih  = (const float*)d_in[2];
    const float* qWhh  = (const float*)d_in[3];
    const float* qbih  = (const float*)d_in[4];
    const float* qbhh  = (const float*)d_in[5];
    const float* kWih  = (const float*)d_in[6];
    const float* kWhh  = (const float*)d_in[7];
    const float* kbih  = (const float*)d_in[8];
    const float* kbhh  = (const float*)d_in[9];
    const float* vWih  = (const float*)d_in[10];
    const float* vWhh  = (const float*)d_in[11];
    const float* vbih  = (const float*)d_in[12];
    const float* vbhh  = (const float*)d_in[13];
    float* out = (float*)d_out;

    cudaFuncSetAttribute(qk_lstm_fp8, cudaFuncAttributeMaxDynamicSharedMemorySize, QK_SMEM);
    cudaFuncSetAttribute(attn_kernel, cudaFuncAttributeMaxDynamicSharedMemorySize, ATTN_SMEM);

    dummy_kernel<<<1, 32>>>();
    xT_kernel<<<(NSEQ * L_DIM + 255) / 256, 256>>>(x);
    v_lstm_kernel<<<dim3((NSEQ + 255) / 256, NH), 256>>>(vWih, vWhh, vbih, vbhh);
    qk_lstm_fp8<<<dim3(NBLK, 16), 256, QK_SMEM>>>(qWih, qWhh, qbih, qbhh,
                                                  kWih, kWhh, kbih, kbhh);
    attn_kernel<<<dim3((S_DIM + 31) / 32, B_DIM, NH), 256, ATTN_SMEM>>>(graph, out);
}

// round 13
// speedup vs baseline: 1.0909x; 1.0909x over previous
#include <cuda_runtime.h>
#include <cuda_fp16.h>
#include <math.h>

#define B_DIM 32
#define S_DIM 325
#define L_DIM 192
#define NSEQ (B_DIM * S_DIM)   // 10400
#define DH 128
#define NH 8
#define NEG_F (-1000000000.0f)

// ---- qk fp16 HMMA kernel geometry ----
#define MSEQ 64                          // sequences per block (2 teams x 32)
#define WSTR 152                         // half-element stride: 144 (128+16 ext) + 8 pad
#define NBLK ((NSEQ + MSEQ - 1) / MSEQ)  // 163
#define SM_W_BYTES (512 * WSTR * 2)      // 155648
#define SM_H_BYTES (MSEQ * WSTR * 2)     // 19456
#define SM_HA SM_W_BYTES
#define SM_HB (SM_W_BYTES + SM_H_BYTES)
#define QK_SMEM (SM_W_BYTES + 2 * SM_H_BYTES)   // 194560 bytes -> 1 block/SM

#define ATTN_SMEM ((32*129 + 32*336 + 32*193) * 4) // 84224 bytes

// ---- scratch (static device arrays; no allocation allowed) ----
__device__ float g_xT[L_DIM * NSEQ];            // x transposed [t][n]
__device__ float g_q[NH * NSEQ * DH];           // [h][n][d]
__device__ float g_k[NH * NSEQ * DH];           // [h][n][d]
__device__ float g_v[NH * NSEQ * L_DIM];        // [h][n][l]

__device__ __forceinline__ float sigf(float x) { return 1.0f / (1.0f + __expf(-x)); }
__device__ __forceinline__ float tanh_fast(float x) { return 2.0f / (1.0f + __expf(-2.0f * x)) - 1.0f; }

__device__ __forceinline__ __half2 tanh2(__half2 x) {
    unsigned y, xi = *(unsigned*)&x;
    asm("tanh.approx.f16x2 %0, %1;" : "=r"(y) : "r"(xi));
    return *(__half2*)&y;
}

__device__ __forceinline__ void ldsm4(unsigned& r0, unsigned& r1, unsigned& r2, unsigned& r3,
                                      const void* p) {
    unsigned a = (unsigned)__cvta_generic_to_shared(p);
    asm volatile("ldmatrix.sync.aligned.m8n8.x4.shared.b16 {%0,%1,%2,%3}, [%4];"
                 : "=r"(r0), "=r"(r1), "=r"(r2), "=r"(r3) : "r"(a));
}
__device__ __forceinline__ void mma16816(float* d, const unsigned* a, unsigned b0, unsigned b1) {
    asm volatile("mma.sync.aligned.m16n8k16.row.col.f32.f16.f16.f32 "
                 "{%0,%1,%2,%3}, {%4,%5,%6,%7}, {%8,%9}, {%0,%1,%2,%3};"
                 : "+f"(d[0]), "+f"(d[1]), "+f"(d[2]), "+f"(d[3])
                 : "r"(a[0]), "r"(a[1]), "r"(a[2]), "r"(a[3]), "r"(b0), "r"(b1));
}

// ---------------- dummy (keeps ncu capture slot on qk kernel) ----------------
__global__ void dummy_kernel() {}

// ---------------- x transpose: [n][t] -> [t][n] ----------------
__global__ void xT_kernel(const float* __restrict__ x) {
    int i = blockIdx.x * 256 + threadIdx.x;
    if (i < NSEQ * L_DIM) {
        int n = i / L_DIM, t = i - n * L_DIM;
        g_xT[t * NSEQ + n] = x[i];
    }
}

// ---------------- v LSTM (hidden size 1) ----------------
__global__ void v_lstm_kernel(const float* __restrict__ Wih, const float* __restrict__ Whh,
                              const float* __restrict__ bih, const float* __restrict__ bhh) {
    int n = blockIdx.x * 256 + threadIdx.x;
    int h = blockIdx.y;
    if (n >= NSEQ) return;
    float wi[4], wh[4], bb[4];
#pragma unroll
    for (int g = 0; g < 4; g++) {
        wi[g] = Wih[h * 4 + g];
        wh[g] = Whh[h * 4 + g];
        bb[g] = bih[h * 4 + g] + bhh[h * 4 + g];
    }
    float hv = 0.f, c = 0.f;
    float4 buf;
    float* vout = g_v + ((size_t)h * NSEQ + n) * L_DIM;
    for (int t = 0; t < L_DIM; t++) {
        float xv = g_xT[t * NSEQ + n];
        float zi = xv * wi[0] + hv * wh[0] + bb[0];
        float zf = xv * wi[1] + hv * wh[1] + bb[1];
        float zg = xv * wi[2] + hv * wh[2] + bb[2];
        float zo = xv * wi[3] + hv * wh[3] + bb[3];
        c = sigf(zf) * c + sigf(zi) * tanh_fast(zg);
        hv = sigf(zo) * tanh_fast(c);
        ((float*)&buf)[t & 3] = hv;
        if ((t & 3) == 3) *(float4*)(vout + (t - 3)) = buf;
    }
}

// ---------------- q/k LSTM on fp16 tensor cores (m16n8k16, K ext-fold) -------
// grid (163, 16). 512 threads = 16 warps. warp = T*8 + wv:
//   T  = M-team (seqs [32T, 32T+32) of the block's 64)
//   wv = N-chunk (permuted gate cols [64wv, 64wv+64) = units [16wv,16wv+16) x 4 gates)
// K extended to 144: A-ext = [x_t, 1, 0...], W-ext = [Wih, b, 0...] so the MMA
// emits the complete pre-activation z; epilogue has no per-thread W/b state.
__global__ __launch_bounds__(512, 1) void qk_lstm_mma(
    const float* __restrict__ qWih, const float* __restrict__ qWhh,
    const float* __restrict__ qbih, const float* __restrict__ qbhh,
    const float* __restrict__ kWih, const float* __restrict__ kWhh,
    const float* __restrict__ kbih, const float* __restrict__ kbhh) {
    extern __shared__ char sm[];
    __half* ws = (__half*)sm;                        // permuted W fp16 [512][WSTR]
    __half* hbufA = (__half*)(sm + SM_HA);           // h [64][WSTR] fp16
    __half* hbufB = (__half*)(sm + SM_HB);

    const int tid = threadIdx.x;
    const int warp = tid >> 5, lane = tid & 31;
    const int T = warp >> 3, wv = warp & 7;
    const int q4 = lane >> 2, r4 = lane & 3;
    const int grp = lane >> 3, ro = lane & 7;
    const int p = blockIdx.y, head = p & 7;
    const bool is_q = p < 8;
    const int n0 = blockIdx.x * MSEQ;

    const float* Wih = (is_q ? qWih : kWih) + head * 512;
    const float* Whh = (is_q ? qWhh : kWhh) + (size_t)head * 512 * 128;
    const float* bih = (is_q ? qbih : kbih) + head * 512;
    const float* bhh = (is_q ? qbhh : kbhh) + head * 512;

    // zero all smem (pad/ext tails and h buffers must start 0)
    for (int i = tid; i < QK_SMEM / 4; i += 512) ((unsigned*)sm)[i] = 0u;
    __syncthreads();

    // stage permuted recurrent weights fp16 (2 elements per thread-iter)
    for (int i = tid; i < 512 * 64; i += 512) {
        int row = i >> 6, kp = i & 63;
        int g = row >> 7, j = row & 127;
        int pcol = (j >> 4) * 64 + (g * 2 + ((j >> 3) & 1)) * 8 + (j & 7);
        *(__half2*)(ws + pcol * WSTR + 2 * kp) =
            __floats2half2_rn(Whh[row * 128 + 2 * kp], Whh[row * 128 + 2 * kp + 1]);
    }
    // ext cols: [Wih, b] at k=128,129
    for (int row = tid; row < 512; row += 512) ;  // (no-op; keep loop shape simple)
    if (tid < 512) {
        int row = tid;
        int g = row >> 7, j = row & 127;
        int pcol = (j >> 4) * 64 + (g * 2 + ((j >> 3) & 1)) * 8 + (j & 7);
        *(__half2*)(ws + pcol * WSTR + 128) =
            __floats2half2_rn(Wih[row], bih[row] + bhh[row]);
    }
    // h buffer 0 ext: [x_0, 1] per row
    if (tid < MSEQ) {
        int n = n0 + tid;
        float x0 = (n < NSEQ) ? g_xT[n] : 0.f;
        *(__half2*)(hbufA + tid * WSTR + 128) = __floats2half2_rn(x0, 1.0f);
    }

    __half2 c2[2][2][2];
#pragma unroll
    for (int m = 0; m < 2; m++)
#pragma unroll
        for (int uh = 0; uh < 2; uh++)
#pragma unroll
            for (int pr = 0; pr < 2; pr++) c2[m][uh][pr] = __floats2half2_rn(0.f, 0.f);

    // ldmatrix lane address components (half-element offsets)
    const int a_row = (grp & 1) * 8 + ro, a_k = (grp >> 1) * 8;
    const int b_row = (grp >> 1) * 8 + ro, b_k = (grp & 1) * 8;
    const int wN0 = wv * 64;
    const __half2 H05 = __floats2half2_rn(0.5f, 0.5f);

    // rolling x prefetch (ext-writer warps wv==0): x_{t+1} during step t
    float xnext = 0.f;
    if (wv == 0) {
        int n = n0 + T * 32 + lane;
        xnext = (n < NSEQ) ? g_xT[NSEQ + n] : 0.f;   // x_1
    }

    __syncthreads();

    for (int t = 0; t < L_DIM; t++) {
        const __half* hc = (t & 1) ? hbufB : hbufA;
        __half* hn = (t & 1) ? hbufA : hbufB;

        float acc[2][8][4];
#pragma unroll
        for (int m = 0; m < 2; m++)
#pragma unroll
            for (int j = 0; j < 8; j++)
#pragma unroll
                for (int e = 0; e < 4; e++) acc[m][j][e] = 0.f;

        // Z = [H | x 1] @ [W | Wih b]^T over K=144 in 9 k16 chunks
#pragma unroll
        for (int kt = 0; kt < 9; kt++) {
            const int koff = kt * 16;
            unsigned a[2][4], b[4][4];
#pragma unroll
            for (int m = 0; m < 2; m++)
                ldsm4(a[m][0], a[m][1], a[m][2], a[m][3],
                      hc + (T * 32 + m * 16 + a_row) * WSTR + koff + a_k);
#pragma unroll
            for (int jj = 0; jj < 4; jj++)
                ldsm4(b[jj][0], b[jj][1], b[jj][2], b[jj][3],
                      ws + (wN0 + jj * 16 + b_row) * WSTR + koff + b_k);
#pragma unroll
            for (int m = 0; m < 2; m++)
#pragma unroll
                for (int jj = 0; jj < 4; jj++) {
                    mma16816(acc[m][2 * jj],     a[m], b[jj][0], b[jj][1]);
                    mma16816(acc[m][2 * jj + 1], a[m], b[jj][2], b[jj][3]);
                }
        }

        // epilogue: acc IS z. LSTM nonlinearity (f16x2), h -> fp16 SMEM
#pragma unroll
        for (int m = 0; m < 2; m++)
#pragma unroll
            for (int pr = 0; pr < 2; pr++) {
                const int rl = m * 16 + q4 + pr * 8;   // row in team
                const int e = 2 * pr;
#pragma unroll
                for (int uh = 0; uh < 2; uh++) {
                    __half2 zi = __floats2half2_rn(acc[m][0 + uh][e], acc[m][0 + uh][e + 1]);
                    __half2 zf = __floats2half2_rn(acc[m][2 + uh][e], acc[m][2 + uh][e + 1]);
                    __half2 zg = __floats2half2_rn(acc[m][4 + uh][e], acc[m][4 + uh][e + 1]);
                    __half2 zo = __floats2half2_rn(acc[m][6 + uh][e], acc[m][6 + uh][e + 1]);
                    __half2 si = __hfma2(tanh2(__hmul2(zi, H05)), H05, H05);
                    __half2 sf = __hfma2(tanh2(__hmul2(zf, H05)), H05, H05);
                    __half2 so = __hfma2(tanh2(__hmul2(zo, H05)), H05, H05);
                    __half2 tg = tanh2(zg);
                    __half2 cc = __hfma2(sf, c2[m][uh][pr], __hmul2(si, tg));
                    c2[m][uh][pr] = cc;
                    __half2 h2 = __hmul2(so, tanh2(cc));
                    const int u0 = 16 * wv + uh * 8 + 2 * r4;
                    const int row = T * 32 + rl;
                    *(__half2*)(hn + row * WSTR + u0) = h2;
                    if (t == L_DIM - 1) {
                        float* ob = (is_q ? g_q : g_k) + (size_t)head * NSEQ * DH;
                        int n1 = n0 + row;
                        if (n1 < NSEQ) {
                            float2 f = __half22float2(h2);
                            ob[(size_t)n1 * DH + u0]     = f.x;
                            ob[(size_t)n1 * DH + u0 + 1] = f.y;
                        }
                    }
                }
            }

        // ext word for t+1: [x_{t+1}, 1]; then prefetch x_{t+2}
        if (wv == 0 && t < L_DIM - 1) {
            int row = T * 32 + lane;
            *(__half2*)(hn + row * WSTR + 128) = __floats2half2_rn(xnext, 1.0f);
            if (t + 2 < L_DIM) {
                int n = n0 + row;
                xnext = (n < NSEQ) ? g_xT[(t + 2) * NSEQ + n] : 0.f;
            }
        }
        __syncthreads();
    }
}

// ---------------- attention: scores + leaky + mask + softmax + AV + leaky ----
__global__ __launch_bounds__(256, 2) void attn_kernel(const float* __restrict__ graph,
                                                      float* __restrict__ out) {
    extern __shared__ char smem_raw[];
    float* qs = (float*)smem_raw;     // [32][129]
    float* sc = qs + 32 * 129;        // [32][336]
    float* kv = sc + 32 * 336;        // [32][193]

    const int tid = threadIdx.x;
    const int h = blockIdx.z, b = blockIdx.y;
    const int s0 = blockIdx.x * 32;
    const int nrows = min(32, S_DIM - s0);
    const int w = tid >> 5, lane = tid & 31;

    for (int i = tid; i < nrows * 128; i += 256) {
        int r = i >> 7, d = i & 127;
        qs[r * 129 + d] = g_q[((size_t)h * NSEQ + (size_t)b * S_DIM + s0 + r) * 128 + d];
    }
    __syncthreads();

    for (int tk = 0; tk < S_DIM; tk += 32) {
        int tw = min(32, S_DIM - tk);
        for (int i = tid; i < tw * 128; i += 256) {
            int r = i >> 7, d = i & 127;
            kv[r * 129 + d] = g_k[((size_t)h * NSEQ + (size_t)b * S_DIM + tk + r) * 128 + d];
        }
        __syncthreads();
        int si = lane;
        int tl0 = w * 4;
        if (si < nrows && tl0 < tw) {
            float a0 = 0, a1 = 0, a2 = 0, a3 = 0;
            const float* qrow = qs + si * 129;
            const float* k0 = kv + tl0 * 129;
#pragma unroll 4
            for (int d = 0; d < 128; d++) {
                float qv = qrow[d];
                a0 = fmaf(qv, k0[d], a0);
                a1 = fmaf(qv, k0[129 + d], a1);
                a2 = fmaf(qv, k0[258 + d], a2);
                a3 = fmaf(qv, k0[387 + d], a3);
            }
            float av[4] = {a0, a1, a2, a3};
#pragma unroll
            for (int j = 0; j < 4; j++) {
                int t = tk + tl0 + j;
                if (t < S_DIM) {
                    float v = av[j] * 0.08838834764831845f;  // 1/sqrt(128)
                    v = (v >= 0.f) ? v : 0.2f * v;           // leaky
                    float gval = graph[(size_t)t * S_DIM + (s0 + si)];
                    if (s0 + si == t) gval += 1.f;
                    if (gval == 0.f) v += NEG_F;             // mask
                    sc[si * 336 + t] = v;
                }
            }
        }
        __syncthreads();
    }

    for (int si = w; si < nrows; si += 8) {
        float* row = sc + si * 336;
        float m = -3.0e38f;
        for (int j = lane; j < S_DIM; j += 32) m = fmaxf(m, row[j]);
#pragma unroll
        for (int o = 16; o; o >>= 1) m = fmaxf(m, __shfl_xor_sync(0xffffffffu, m, o));
        float ssum = 0.f;
        for (int j = lane; j < S_DIM; j += 32) {
            float e = __expf(row[j] - m);
            row[j] = e;
            ssum += e;
        }
#pragma unroll
        for (int o = 16; o; o >>= 1) ssum += __shfl_xor_sync(0xffffffffu, ssum, o);
        float inv = 1.0f / ssum;
        for (int j = lane; j < S_DIM; j += 32) row[j] *= inv;
    }
    __syncthreads();

    float acc[24];
#pragma unroll
    for (int j = 0; j < 24; j++) acc[j] = 0.f;
    const int si2 = tid >> 3;
    const int lq = tid & 7;
    for (int tk = 0; tk < S_DIM; tk += 32) {
        int tw = min(32, S_DIM - tk);
        for (int i = tid; i < tw * 192; i += 256) {
            int r = i / 192, l = i - r * 192;
            kv[r * 193 + l] = g_v[((size_t)h * NSEQ + (size_t)b * S_DIM + tk + r) * 192 + l];
        }
        __syncthreads();
        if (si2 < nrows) {
            for (int t = 0; t < tw; t++) {
                float a = sc[si2 * 336 + tk + t];
                const float* vrow = kv + t * 193 + lq;
#pragma unroll
                for (int j = 0; j < 24; j++) acc[j] = fmaf(a, vrow[8 * j], acc[j]);
            }
        }
        __syncthreads();
    }
    if (si2 < nrows) {
        size_t base = ((size_t)(b * S_DIM + s0 + si2) * 192) * 8 + h;
#pragma unroll
        for (int j = 0; j < 24; j++) {
            float v = acc[j];
            v = (v >= 0.f) ? v : 0.2f * v;  // final leaky
            out[base + (size_t)(lq + 8 * j) * 8] = v;
        }
    }
}

extern "C" void kernel_launch(void* const* d_in, const int* in_sizes, int n_in,
                              void* d_out, int out_size) {
    const float* x     = (const float*)d_in[0];
    const float* graph = (const float*)d_in[1];
    const float* qWih  = (const float*)d_in[2];
    const float* qWhh  = (const float*)d_in[3];
    const float* qbih  = (const float*)d_in[4];
    const float* qbhh  = (const float*)d_in[5];
    const float* kWih  = (const float*)d_in[6];
    const float* kWhh  = (const float*)d_in[7];
    const float* kbih  = (const float*)d_in[8];
    const float* kbhh  = (const float*)d_in[9];
    const float* vWih  = (const float*)d_in[10];
    const float* vWhh  = (const float*)d_in[11];
    const float* vbih  = (const float*)d_in[12];
    const float* vbhh  = (const float*)d_in[13];
    float* out = (float*)d_out;

    cudaFuncSetAttribute(qk_lstm_mma, cudaFuncAttributeMaxDynamicSharedMemorySize, QK_SMEM);
    cudaFuncSetAttribute(attn_kernel, cudaFuncAttributeMaxDynamicSharedMemorySize, ATTN_SMEM);

    dummy_kernel<<<1, 32>>>();
    xT_kernel<<<(NSEQ * L_DIM + 255) / 256, 256>>>(x);
    v_lstm_kernel<<<dim3((NSEQ + 255) / 256, NH), 256>>>(vWih, vWhh, vbih, vbhh);
    qk_lstm_mma<<<dim3(NBLK, 16), 512, QK_SMEM>>>(qWih, qWhh, qbih, qbhh,
                                                  kWih, kWhh, kbih, kbhh);
    attn_kernel<<<dim3((S_DIM + 31) / 32, B_DIM, NH), 256, ATTN_SMEM>>>(graph, out);
}

// round 14
// speedup vs baseline: 1.2649x; 1.1595x over previous
#include <cuda_runtime.h>
#include <cuda_fp16.h>
#include <math.h>

#define B_DIM 32
#define S_DIM 325
#define L_DIM 192
#define NSEQ (B_DIM * S_DIM)   // 10400
#define DH 128
#define NH 8
#define NEG_F (-1000000000.0f)

// ---- qk fp16 HMMA kernel geometry ----
#define MSEQ 64                          // sequences per block (2 teams x 32)
#define WSTR 136                         // half stride: 128 + 8 pad
#define NBLK ((NSEQ + MSEQ - 1) / MSEQ)  // 163
#define SM_W_BYTES (512 * WSTR * 2)      // 139264
#define SM_H_BYTES (MSEQ * WSTR * 2)     // 17408
#define SM_HA SM_W_BYTES
#define SM_HB (SM_W_BYTES + SM_H_BYTES)
#define SM_XS (SM_W_BYTES + 2 * SM_H_BYTES)
#define QK_SMEM (SM_XS + 2 * MSEQ * 4)   // 174592 bytes -> 1 block/SM

#define ATTN_SMEM ((32*129 + 32*336 + 32*193) * 4) // 84224 bytes

// ---- scratch (static device arrays; no allocation allowed) ----
__device__ float g_xT[L_DIM * NSEQ];            // x transposed [t][n]
__device__ float g_q[NH * NSEQ * DH];           // [h][n][d]
__device__ float g_k[NH * NSEQ * DH];           // [h][n][d]
__device__ float g_v[NH * NSEQ * L_DIM];        // [h][n][l]

__device__ __forceinline__ float sigf(float x) { return 1.0f / (1.0f + __expf(-x)); }
__device__ __forceinline__ float tanh_fast(float x) { return 2.0f / (1.0f + __expf(-2.0f * x)) - 1.0f; }

__device__ __forceinline__ __half2 tanh2(__half2 x) {
    unsigned y, xi = *(unsigned*)&x;
    asm("tanh.approx.f16x2 %0, %1;" : "=r"(y) : "r"(xi));
    return *(__half2*)&y;
}

__device__ __forceinline__ void ldsm4(unsigned& r0, unsigned& r1, unsigned& r2, unsigned& r3,
                                      const void* p) {
    unsigned a = (unsigned)__cvta_generic_to_shared(p);
    asm volatile("ldmatrix.sync.aligned.m8n8.x4.shared.b16 {%0,%1,%2,%3}, [%4];"
                 : "=r"(r0), "=r"(r1), "=r"(r2), "=r"(r3) : "r"(a));
}
// f16-accumulator HMMA: D,C are 2x f16x2 regs
__device__ __forceinline__ void mma16816h(unsigned* d, const unsigned* a, unsigned b0, unsigned b1) {
    asm volatile("mma.sync.aligned.m16n8k16.row.col.f16.f16.f16.f16 "
                 "{%0,%1}, {%2,%3,%4,%5}, {%6,%7}, {%0,%1};"
                 : "+r"(d[0]), "+r"(d[1])
                 : "r"(a[0]), "r"(a[1]), "r"(a[2]), "r"(a[3]), "r"(b0), "r"(b1));
}

// ---------------- dummy (keeps ncu capture slot on qk kernel) ----------------
__global__ void dummy_kernel() {}

// ---------------- x transpose: [n][t] -> [t][n] ----------------
__global__ void xT_kernel(const float* __restrict__ x) {
    int i = blockIdx.x * 256 + threadIdx.x;
    if (i < NSEQ * L_DIM) {
        int n = i / L_DIM, t = i - n * L_DIM;
        g_xT[t * NSEQ + n] = x[i];
    }
}

// ---------------- v LSTM (hidden size 1) ----------------
__global__ void v_lstm_kernel(const float* __restrict__ Wih, const float* __restrict__ Whh,
                              const float* __restrict__ bih, const float* __restrict__ bhh) {
    int n = blockIdx.x * 256 + threadIdx.x;
    int h = blockIdx.y;
    if (n >= NSEQ) return;
    float wi[4], wh[4], bb[4];
#pragma unroll
    for (int g = 0; g < 4; g++) {
        wi[g] = Wih[h * 4 + g];
        wh[g] = Whh[h * 4 + g];
        bb[g] = bih[h * 4 + g] + bhh[h * 4 + g];
    }
    float hv = 0.f, c = 0.f;
    float4 buf;
    float* vout = g_v + ((size_t)h * NSEQ + n) * L_DIM;
    for (int t = 0; t < L_DIM; t++) {
        float xv = g_xT[t * NSEQ + n];
        float zi = xv * wi[0] + hv * wh[0] + bb[0];
        float zf = xv * wi[1] + hv * wh[1] + bb[1];
        float zg = xv * wi[2] + hv * wh[2] + bb[2];
        float zo = xv * wi[3] + hv * wh[3] + bb[3];
        c = sigf(zf) * c + sigf(zi) * tanh_fast(zg);
        hv = sigf(zo) * tanh_fast(c);
        ((float*)&buf)[t & 3] = hv;
        if ((t & 3) == 3) *(float4*)(vout + (t - 3)) = buf;
    }
}

// ---------------- q/k LSTM on fp16 tensor cores (m16n8k16, f16 acc) ----------
// grid (163, 16). 512 threads = 16 warps. warp = T*8 + wv:
//   T  = M-team (seqs [32T, 32T+32) of the block's 64)
//   wv = N-chunk (permuted gate cols [64wv, 64wv+64) = units [16wv,16wv+16) x 4 gates)
// f16 accumulators (double-rate HMMA); bias + x*Wih folded into C-operand init.
// f16-D fragment: reg0 = cols (2r4,2r4+1) of row q4; reg1 = same cols of row q4+8.
__global__ __launch_bounds__(512, 1) void qk_lstm_mma(
    const float* __restrict__ qWih, const float* __restrict__ qWhh,
    const float* __restrict__ qbih, const float* __restrict__ qbhh,
    const float* __restrict__ kWih, const float* __restrict__ kWhh,
    const float* __restrict__ kbih, const float* __restrict__ kbhh) {
    extern __shared__ char sm[];
    __half* ws = (__half*)sm;                        // permuted W fp16 [512][WSTR]
    __half* hbufA = (__half*)(sm + SM_HA);           // h [64][WSTR] fp16
    __half* hbufB = (__half*)(sm + SM_HB);
    float* xs = (float*)(sm + SM_XS);                // x ring [2][64]

    const int tid = threadIdx.x;
    const int warp = tid >> 5, lane = tid & 31;
    const int T = warp >> 3, wv = warp & 7;
    const int q4 = lane >> 2, r4 = lane & 3;
    const int grp = lane >> 3, ro = lane & 7;
    const int p = blockIdx.y, head = p & 7;
    const bool is_q = p < 8;
    const int n0 = blockIdx.x * MSEQ;

    const float* Wih = (is_q ? qWih : kWih) + head * 512;
    const float* Whh = (is_q ? qWhh : kWhh) + (size_t)head * 512 * 128;
    const float* bih = (is_q ? qbih : kbih) + head * 512;
    const float* bhh = (is_q ? qbhh : kbhh) + head * 512;

    // zero all smem (pad tails and h buffers must start 0)
    for (int i = tid; i < QK_SMEM / 4; i += 512) ((unsigned*)sm)[i] = 0u;
    __syncthreads();

    // stage permuted recurrent weights fp16
    for (int i = tid; i < 512 * 64; i += 512) {
        int row = i >> 6, kp = i & 63;
        int g = row >> 7, j = row & 127;
        int pcol = (j >> 4) * 64 + (g * 2 + ((j >> 3) & 1)) * 8 + (j & 7);
        *(__half2*)(ws + pcol * WSTR + 2 * kp) =
            __floats2half2_rn(Whh[row * 128 + 2 * kp], Whh[row * 128 + 2 * kp + 1]);
    }
    // prime x for t=0
    if (tid < MSEQ) {
        int n = n0 + tid;
        xs[tid] = (n < NSEQ) ? g_xT[n] : 0.f;
    }

    // per-thread input weights / biases in half2 (nt = gate*2 + uh; covers the
    // thread's column pair = units 16wv + uh*8 + 2r4, +1)
    __half2 wih2[8], b2[8];
#pragma unroll
    for (int nt = 0; nt < 8; nt++) {
        int g = nt >> 1, uh = nt & 1;
        int u = 16 * wv + uh * 8 + 2 * r4;
        int r0 = g * 128 + u;
        wih2[nt] = __floats2half2_rn(Wih[r0], Wih[r0 + 1]);
        b2[nt] = __floats2half2_rn(bih[r0] + bhh[r0], bih[r0 + 1] + bhh[r0 + 1]);
    }

    __half2 c2[2][2][2];  // [m][uh][pr]
#pragma unroll
    for (int m = 0; m < 2; m++)
#pragma unroll
        for (int uh = 0; uh < 2; uh++)
#pragma unroll
            for (int pr = 0; pr < 2; pr++) c2[m][uh][pr] = __floats2half2_rn(0.f, 0.f);

    // ldmatrix lane address components (half-element offsets)
    const int a_row = (grp & 1) * 8 + ro, a_k = (grp >> 1) * 8;
    const int b_row = (grp >> 1) * 8 + ro, b_k = (grp & 1) * 8;
    const int wN0 = wv * 64;
    const __half2 H05 = __floats2half2_rn(0.5f, 0.5f);

    // rolling x prefetch (wv==0 warps, one per team): x_{t+1} during step t
    float xnext = 0.f;
    if (wv == 0) {
        int n = n0 + T * 32 + lane;
        xnext = (n < NSEQ) ? g_xT[NSEQ + n] : 0.f;   // x_1
    }

    __syncthreads();

    for (int t = 0; t < L_DIM; t++) {
        const __half* hc = (t & 1) ? hbufB : hbufA;
        __half* hn = (t & 1) ? hbufA : hbufB;

        // C-operand init: z = b + x * Wih (f16x2). reg pr covers row q4+8*pr.
        unsigned acc[2][8][2];
        const float* xrow = xs + (t & 1) * MSEQ + T * 32;
#pragma unroll
        for (int m = 0; m < 2; m++) {
            const __half2 x0 = __float2half2_rn(xrow[m * 16 + q4]);
            const __half2 x1 = __float2half2_rn(xrow[m * 16 + q4 + 8]);
#pragma unroll
            for (int nt = 0; nt < 8; nt++) {
                __half2 v0 = __hfma2(x0, wih2[nt], b2[nt]);
                __half2 v1 = __hfma2(x1, wih2[nt], b2[nt]);
                acc[m][nt][0] = *(unsigned*)&v0;
                acc[m][nt][1] = *(unsigned*)&v1;
            }
        }

        // Z += H @ W^T over K=128 in 8 k16 chunks
#pragma unroll
        for (int kt = 0; kt < 8; kt++) {
            const int koff = kt * 16;
            unsigned a[2][4], b[4][4];
#pragma unroll
            for (int m = 0; m < 2; m++)
                ldsm4(a[m][0], a[m][1], a[m][2], a[m][3],
                      hc + (T * 32 + m * 16 + a_row) * WSTR + koff + a_k);
#pragma unroll
            for (int jj = 0; jj < 4; jj++)
                ldsm4(b[jj][0], b[jj][1], b[jj][2], b[jj][3],
                      ws + (wN0 + jj * 16 + b_row) * WSTR + koff + b_k);
#pragma unroll
            for (int m = 0; m < 2; m++)
#pragma unroll
                for (int jj = 0; jj < 4; jj++) {
                    mma16816h(acc[m][2 * jj],     a[m], b[jj][0], b[jj][1]);
                    mma16816h(acc[m][2 * jj + 1], a[m], b[jj][2], b[jj][3]);
                }
        }

        // epilogue: acc IS z (f16x2). LSTM nonlinearity, h -> fp16 SMEM
#pragma unroll
        for (int m = 0; m < 2; m++)
#pragma unroll
            for (int pr = 0; pr < 2; pr++) {
                const int rl = m * 16 + q4 + pr * 8;   // row in team
#pragma unroll
                for (int uh = 0; uh < 2; uh++) {
                    __half2 zi = *(__half2*)&acc[m][0 + uh][pr];
                    __half2 zf = *(__half2*)&acc[m][2 + uh][pr];
                    __half2 zg = *(__half2*)&acc[m][4 + uh][pr];
                    __half2 zo = *(__half2*)&acc[m][6 + uh][pr];
                    __half2 si = __hfma2(tanh2(__hmul2(zi, H05)), H05, H05);
                    __half2 sf = __hfma2(tanh2(__hmul2(zf, H05)), H05, H05);
                    __half2 so = __hfma2(tanh2(__hmul2(zo, H05)), H05, H05);
                    __half2 tg = tanh2(zg);
                    __half2 cc = __hfma2(sf, c2[m][uh][pr], __hmul2(si, tg));
                    c2[m][uh][pr] = cc;
                    __half2 h2 = __hmul2(so, tanh2(cc));
                    const int u0 = 16 * wv + uh * 8 + 2 * r4;
                    const int row = T * 32 + rl;
                    *(__half2*)(hn + row * WSTR + u0) = h2;
                    if (t == L_DIM - 1) {
                        float* ob = (is_q ? g_q : g_k) + (size_t)head * NSEQ * DH;
                        int n1 = n0 + row;
                        if (n1 < NSEQ) {
                            float2 f = __half22float2(h2);
                            ob[(size_t)n1 * DH + u0]     = f.x;
                            ob[(size_t)n1 * DH + u0 + 1] = f.y;
                        }
                    }
                }
            }

        // x ring for t+1; prefetch x_{t+2}
        if (wv == 0 && t < L_DIM - 1) {
            xs[((t + 1) & 1) * MSEQ + T * 32 + lane] = xnext;
            if (t + 2 < L_DIM) {
                int n = n0 + T * 32 + lane;
                xnext = (n < NSEQ) ? g_xT[(t + 2) * NSEQ + n] : 0.f;
            }
        }
        __syncthreads();
    }
}

// ---------------- attention: scores + leaky + mask + softmax + AV + leaky ----
__global__ __launch_bounds__(256, 2) void attn_kernel(const float* __restrict__ graph,
                                                      float* __restrict__ out) {
    extern __shared__ char smem_raw[];
    float* qs = (float*)smem_raw;     // [32][129]
    float* sc = qs + 32 * 129;        // [32][336]
    float* kv = sc + 32 * 336;        // [32][193]

    const int tid = threadIdx.x;
    const int h = blockIdx.z, b = blockIdx.y;
    const int s0 = blockIdx.x * 32;
    const int nrows = min(32, S_DIM - s0);
    const int w = tid >> 5, lane = tid & 31;

    for (int i = tid; i < nrows * 128; i += 256) {
        int r = i >> 7, d = i & 127;
        qs[r * 129 + d] = g_q[((size_t)h * NSEQ + (size_t)b * S_DIM + s0 + r) * 128 + d];
    }
    __syncthreads();

    for (int tk = 0; tk < S_DIM; tk += 32) {
        int tw = min(32, S_DIM - tk);
        for (int i = tid; i < tw * 128; i += 256) {
            int r = i >> 7, d = i & 127;
            kv[r * 129 + d] = g_k[((size_t)h * NSEQ + (size_t)b * S_DIM + tk + r) * 128 + d];
        }
        __syncthreads();
        int si = lane;
        int tl0 = w * 4;
        if (si < nrows && tl0 < tw) {
            float a0 = 0, a1 = 0, a2 = 0, a3 = 0;
            const float* qrow = qs + si * 129;
            const float* k0 = kv + tl0 * 129;
#pragma unroll 4
            for (int d = 0; d < 128; d++) {
                float qv = qrow[d];
                a0 = fmaf(qv, k0[d], a0);
                a1 = fmaf(qv, k0[129 + d], a1);
                a2 = fmaf(qv, k0[258 + d], a2);
                a3 = fmaf(qv, k0[387 + d], a3);
            }
            float av[4] = {a0, a1, a2, a3};
#pragma unroll
            for (int j = 0; j < 4; j++) {
                int t = tk + tl0 + j;
                if (t < S_DIM) {
                    float v = av[j] * 0.08838834764831845f;  // 1/sqrt(128)
                    v = (v >= 0.f) ? v : 0.2f * v;           // leaky
                    float gval = graph[(size_t)t * S_DIM + (s0 + si)];
                    if (s0 + si == t) gval += 1.f;
                    if (gval == 0.f) v += NEG_F;             // mask
                    sc[si * 336 + t] = v;
                }
            }
        }
        __syncthreads();
    }

    for (int si = w; si < nrows; si += 8) {
        float* row = sc + si * 336;
        float m = -3.0e38f;
        for (int j = lane; j < S_DIM; j += 32) m = fmaxf(m, row[j]);
#pragma unroll
        for (int o = 16; o; o >>= 1) m = fmaxf(m, __shfl_xor_sync(0xffffffffu, m, o));
        float ssum = 0.f;
        for (int j = lane; j < S_DIM; j += 32) {
            float e = __expf(row[j] - m);
            row[j] = e;
            ssum += e;
        }
#pragma unroll
        for (int o = 16; o; o >>= 1) ssum += __shfl_xor_sync(0xffffffffu, ssum, o);
        float inv = 1.0f / ssum;
        for (int j = lane; j < S_DIM; j += 32) row[j] *= inv;
    }
    __syncthreads();

    float acc[24];
#pragma unroll
    for (int j = 0; j < 24; j++) acc[j] = 0.f;
    const int si2 = tid >> 3;
    const int lq = tid & 7;
    for (int tk = 0; tk < S_DIM; tk += 32) {
        int tw = min(32, S_DIM - tk);
        for (int i = tid; i < tw * 192; i += 256) {
            int r = i / 192, l = i - r * 192;
            kv[r * 193 + l] = g_v[((size_t)h * NSEQ + (size_t)b * S_DIM + tk + r) * 192 + l];
        }
        __syncthreads();
        if (si2 < nrows) {
            for (int t = 0; t < tw; t++) {
                float a = sc[si2 * 336 + tk + t];
                const float* vrow = kv + t * 193 + lq;
#pragma unroll
                for (int j = 0; j < 24; j++) acc[j] = fmaf(a, vrow[8 * j], acc[j]);
            }
        }
        __syncthreads();
    }
    if (si2 < nrows) {
        size_t base = ((size_t)(b * S_DIM + s0 + si2) * 192) * 8 + h;
#pragma unroll
        for (int j = 0; j < 24; j++) {
            float v = acc[j];
            v = (v >= 0.f) ? v : 0.2f * v;  // final leaky
            out[base + (size_t)(lq + 8 * j) * 8] = v;
        }
    }
}

extern "C" void kernel_launch(void* const* d_in, const int* in_sizes, int n_in,
                              void* d_out, int out_size) {
    const float* x     = (const float*)d_in[0];
    const float* graph = (const float*)d_in[1];
    const float* qWih  = (const float*)d_in[2];
    const float* qWhh  = (const float*)d_in[3];
    const float* qbih  = (const float*)d_in[4];
    const float* qbhh  = (const float*)d_in[5];
    const float* kWih  = (const float*)d_in[6];
    const float* kWhh  = (const float*)d_in[7];
    const float* kbih  = (const float*)d_in[8];
    const float* kbhh  = (const float*)d_in[9];
    const float* vWih  = (const float*)d_in[10];
    const float* vWhh  = (const float*)d_in[11];
    const float* vbih  = (const float*)d_in[12];
    const float* vbhh  = (const float*)d_in[13];
    float* out = (float*)d_out;

    cudaFuncSetAttribute(qk_lstm_mma, cudaFuncAttributeMaxDynamicSharedMemorySize, QK_SMEM);
    cudaFuncSetAttribute(attn_kernel, cudaFuncAttributeMaxDynamicSharedMemorySize, ATTN_SMEM);

    dummy_kernel<<<1, 32>>>();
    xT_kernel<<<(NSEQ * L_DIM + 255) / 256, 256>>>(x);
    v_lstm_kernel<<<dim3((NSEQ + 255) / 256, NH), 256>>>(vWih, vWhh, vbih, vbhh);
    qk_lstm_mma<<<dim3(NBLK, 16), 512, QK_SMEM>>>(qWih, qWhh, qbih, qbhh,
                                                  kWih, kWhh, kbih, kbhh);
    attn_kernel<<<dim3((S_DIM + 31) / 32, B_DIM, NH), 256, ATTN_SMEM>>>(graph, out);
}

// round 15
// speedup vs baseline: 1.3031x; 1.0302x over previous
#include <cuda_runtime.h>
#include <cuda_fp16.h>
#include <math.h>

#define B_DIM 32
#define S_DIM 325
#define L_DIM 192
#define NSEQ (B_DIM * S_DIM)   // 10400
#define DH 128
#define NH 8
#define NEG_F (-1000000000.0f)

// ---- qk fp16 HMMA kernel geometry ----
#define MSEQ 64                          // sequences per block (2 teams x 32)
#define WSTR 136                         // half stride: 128 + 8 pad
#define NBLK ((NSEQ + MSEQ - 1) / MSEQ)  // 163
#define SM_W_BYTES (512 * WSTR * 2)      // 139264
#define SM_H_BYTES (MSEQ * WSTR * 2)     // 17408
#define SM_HA SM_W_BYTES
#define SM_HB (SM_W_BYTES + SM_H_BYTES)
#define SM_XS (SM_W_BYTES + 2 * SM_H_BYTES)
#define QK_SMEM (SM_XS + 2 * MSEQ * 4)   // 174592 bytes -> 1 block/SM

#define ATTN_SMEM ((32*129 + 32*336 + 32*193) * 4) // 84224 bytes

// ---- scratch (static device arrays; no allocation allowed) ----
__device__ float g_xT[L_DIM * NSEQ];            // x transposed [t][n]
__device__ float g_q[NH * NSEQ * DH];           // [h][n][d]
__device__ float g_k[NH * NSEQ * DH];           // [h][n][d]
__device__ float g_v[NH * NSEQ * L_DIM];        // [h][n][l]

__device__ __forceinline__ float sigf(float x) { return 1.0f / (1.0f + __expf(-x)); }
__device__ __forceinline__ float tanh_fast(float x) { return 2.0f / (1.0f + __expf(-2.0f * x)) - 1.0f; }

__device__ __forceinline__ __half2 tanh2(__half2 x) {
    unsigned y, xi = *(unsigned*)&x;
    asm("tanh.approx.f16x2 %0, %1;" : "=r"(y) : "r"(xi));
    return *(__half2*)&y;
}

__device__ __forceinline__ void ldsm4(unsigned& r0, unsigned& r1, unsigned& r2, unsigned& r3,
                                      const void* p) {
    unsigned a = (unsigned)__cvta_generic_to_shared(p);
    asm volatile("ldmatrix.sync.aligned.m8n8.x4.shared.b16 {%0,%1,%2,%3}, [%4];"
                 : "=r"(r0), "=r"(r1), "=r"(r2), "=r"(r3) : "r"(a));
}
// f16-accumulator HMMA: D,C are 2x f16x2 regs
__device__ __forceinline__ void mma16816h(unsigned* d, const unsigned* a, unsigned b0, unsigned b1) {
    asm volatile("mma.sync.aligned.m16n8k16.row.col.f16.f16.f16.f16 "
                 "{%0,%1}, {%2,%3,%4,%5}, {%6,%7}, {%0,%1};"
                 : "+r"(d[0]), "+r"(d[1])
                 : "r"(a[0]), "r"(a[1]), "r"(a[2]), "r"(a[3]), "r"(b0), "r"(b1));
}
__device__ __forceinline__ void team_bar(int T) {
    asm volatile("bar.sync %0, 256;" :: "r"(1 + T) : "memory");
}

// ---------------- dummy (keeps ncu capture slot on qk kernel) ----------------
__global__ void dummy_kernel() {}

// ---------------- x transpose: [n][t] -> [t][n] ----------------
__global__ void xT_kernel(const float* __restrict__ x) {
    int i = blockIdx.x * 256 + threadIdx.x;
    if (i < NSEQ * L_DIM) {
        int n = i / L_DIM, t = i - n * L_DIM;
        g_xT[t * NSEQ + n] = x[i];
    }
}

// ---------------- v LSTM (hidden size 1) ----------------
__global__ void v_lstm_kernel(const float* __restrict__ Wih, const float* __restrict__ Whh,
                              const float* __restrict__ bih, const float* __restrict__ bhh) {
    int n = blockIdx.x * 256 + threadIdx.x;
    int h = blockIdx.y;
    if (n >= NSEQ) return;
    float wi[4], wh[4], bb[4];
#pragma unroll
    for (int g = 0; g < 4; g++) {
        wi[g] = Wih[h * 4 + g];
        wh[g] = Whh[h * 4 + g];
        bb[g] = bih[h * 4 + g] + bhh[h * 4 + g];
    }
    float hv = 0.f, c = 0.f;
    float4 buf;
    float* vout = g_v + ((size_t)h * NSEQ + n) * L_DIM;
    for (int t = 0; t < L_DIM; t++) {
        float xv = g_xT[t * NSEQ + n];
        float zi = xv * wi[0] + hv * wh[0] + bb[0];
        float zf = xv * wi[1] + hv * wh[1] + bb[1];
        float zg = xv * wi[2] + hv * wh[2] + bb[2];
        float zo = xv * wi[3] + hv * wh[3] + bb[3];
        c = sigf(zf) * c + sigf(zi) * tanh_fast(zg);
        hv = sigf(zo) * tanh_fast(c);
        ((float*)&buf)[t & 3] = hv;
        if ((t & 3) == 3) *(float4*)(vout + (t - 3)) = buf;
    }
}

// ---------------- q/k LSTM on fp16 tensor cores (m16n8k16, f16 acc) ----------
// grid (163, 16). 512 threads = 16 warps. warp = T*8 + wv:
//   T  = M-team (seqs [32T, 32T+32) of the block's 64)
//   wv = N-chunk (permuted gate cols [64wv, 64wv+64) = units [16wv,16wv+16) x 4 gates)
// f16 accumulators; bias + x*Wih folded into C-operand init. Teams are fully
// data-independent (disjoint h rows, own x slice, shared read-only W), so each
// syncs on its OWN named barrier -> teams drift out of phase and one team's
// MUFU/LDSM hides under the other team's HMMA on each SMSP.
__global__ __launch_bounds__(512, 1) void qk_lstm_mma(
    const float* __restrict__ qWih, const float* __restrict__ qWhh,
    const float* __restrict__ qbih, const float* __restrict__ qbhh,
    const float* __restrict__ kWih, const float* __restrict__ kWhh,
    const float* __restrict__ kbih, const float* __restrict__ kbhh) {
    extern __shared__ char sm[];
    __half* ws = (__half*)sm;                        // permuted W fp16 [512][WSTR]
    __half* hbufA = (__half*)(sm + SM_HA);           // h [64][WSTR] fp16
    __half* hbufB = (__half*)(sm + SM_HB);
    float* xs = (float*)(sm + SM_XS);                // x ring [2][64]

    const int tid = threadIdx.x;
    const int warp = tid >> 5, lane = tid & 31;
    const int T = warp >> 3, wv = warp & 7;
    const int q4 = lane >> 2, r4 = lane & 3;
    const int grp = lane >> 3, ro = lane & 7;
    const int p = blockIdx.y, head = p & 7;
    const bool is_q = p < 8;
    const int n0 = blockIdx.x * MSEQ;

    const float* Wih = (is_q ? qWih : kWih) + head * 512;
    const float* Whh = (is_q ? qWhh : kWhh) + (size_t)head * 512 * 128;
    const float* bih = (is_q ? qbih : kbih) + head * 512;
    const float* bhh = (is_q ? qbhh : kbhh) + head * 512;

    // zero all smem (pad tails and h buffers must start 0)
    for (int i = tid; i < QK_SMEM / 4; i += 512) ((unsigned*)sm)[i] = 0u;
    __syncthreads();

    // stage permuted recurrent weights fp16
    for (int i = tid; i < 512 * 64; i += 512) {
        int row = i >> 6, kp = i & 63;
        int g = row >> 7, j = row & 127;
        int pcol = (j >> 4) * 64 + (g * 2 + ((j >> 3) & 1)) * 8 + (j & 7);
        *(__half2*)(ws + pcol * WSTR + 2 * kp) =
            __floats2half2_rn(Whh[row * 128 + 2 * kp], Whh[row * 128 + 2 * kp + 1]);
    }
    // prime x for t=0
    if (tid < MSEQ) {
        int n = n0 + tid;
        xs[tid] = (n < NSEQ) ? g_xT[n] : 0.f;
    }

    // per-thread input weights / biases in half2 (nt = gate*2 + uh; covers the
    // thread's column pair = units 16wv + uh*8 + 2r4, +1)
    __half2 wih2[8], b2[8];
#pragma unroll
    for (int nt = 0; nt < 8; nt++) {
        int g = nt >> 1, uh = nt & 1;
        int u = 16 * wv + uh * 8 + 2 * r4;
        int r0 = g * 128 + u;
        wih2[nt] = __floats2half2_rn(Wih[r0], Wih[r0 + 1]);
        b2[nt] = __floats2half2_rn(bih[r0] + bhh[r0], bih[r0 + 1] + bhh[r0 + 1]);
    }

    __half2 c2[2][2][2];  // [m][uh][pr]
#pragma unroll
    for (int m = 0; m < 2; m++)
#pragma unroll
        for (int uh = 0; uh < 2; uh++)
#pragma unroll
            for (int pr = 0; pr < 2; pr++) c2[m][uh][pr] = __floats2half2_rn(0.f, 0.f);

    // ldmatrix lane address components (half-element offsets)
    const int a_row = (grp & 1) * 8 + ro, a_k = (grp >> 1) * 8;
    const int b_row = (grp >> 1) * 8 + ro, b_k = (grp & 1) * 8;
    const int wN0 = wv * 64;
    const __half2 H05 = __floats2half2_rn(0.5f, 0.5f);

    // rolling x prefetch (wv==0 warps, one per team): x_{t+1} during step t
    float xnext = 0.f;
    if (wv == 0) {
        int n = n0 + T * 32 + lane;
        xnext = (n < NSEQ) ? g_xT[NSEQ + n] : 0.f;   // x_1
    }

    __syncthreads();   // W staged by whole block: last block-wide barrier

    for (int t = 0; t < L_DIM; t++) {
        const __half* hc = (t & 1) ? hbufB : hbufA;
        __half* hn = (t & 1) ? hbufA : hbufB;

        // C-operand init: z = b + x * Wih (f16x2). reg pr covers row q4+8*pr.
        unsigned acc[2][8][2];
        const float* xrow = xs + (t & 1) * MSEQ + T * 32;
#pragma unroll
        for (int m = 0; m < 2; m++) {
            const __half2 x0 = __float2half2_rn(xrow[m * 16 + q4]);
            const __half2 x1 = __float2half2_rn(xrow[m * 16 + q4 + 8]);
#pragma unroll
            for (int nt = 0; nt < 8; nt++) {
                __half2 v0 = __hfma2(x0, wih2[nt], b2[nt]);
                __half2 v1 = __hfma2(x1, wih2[nt], b2[nt]);
                acc[m][nt][0] = *(unsigned*)&v0;
                acc[m][nt][1] = *(unsigned*)&v1;
            }
        }

        // Z += H @ W^T over K=128 in 8 k16 chunks (team's own 32 rows)
#pragma unroll
        for (int kt = 0; kt < 8; kt++) {
            const int koff = kt * 16;
            unsigned a[2][4], b[4][4];
#pragma unroll
            for (int m = 0; m < 2; m++)
                ldsm4(a[m][0], a[m][1], a[m][2], a[m][3],
                      hc + (T * 32 + m * 16 + a_row) * WSTR + koff + a_k);
#pragma unroll
            for (int jj = 0; jj < 4; jj++)
                ldsm4(b[jj][0], b[jj][1], b[jj][2], b[jj][3],
                      ws + (wN0 + jj * 16 + b_row) * WSTR + koff + b_k);
#pragma unroll
            for (int m = 0; m < 2; m++)
#pragma unroll
                for (int jj = 0; jj < 4; jj++) {
                    mma16816h(acc[m][2 * jj],     a[m], b[jj][0], b[jj][1]);
                    mma16816h(acc[m][2 * jj + 1], a[m], b[jj][2], b[jj][3]);
                }
        }

        // epilogue: acc IS z (f16x2). LSTM nonlinearity, h -> fp16 SMEM
#pragma unroll
        for (int m = 0; m < 2; m++)
#pragma unroll
            for (int pr = 0; pr < 2; pr++) {
                const int rl = m * 16 + q4 + pr * 8;   // row in team
#pragma unroll
                for (int uh = 0; uh < 2; uh++) {
                    __half2 zi = *(__half2*)&acc[m][0 + uh][pr];
                    __half2 zf = *(__half2*)&acc[m][2 + uh][pr];
                    __half2 zg = *(__half2*)&acc[m][4 + uh][pr];
                    __half2 zo = *(__half2*)&acc[m][6 + uh][pr];
                    __half2 si = __hfma2(tanh2(__hmul2(zi, H05)), H05, H05);
                    __half2 sf = __hfma2(tanh2(__hmul2(zf, H05)), H05, H05);
                    __half2 so = __hfma2(tanh2(__hmul2(zo, H05)), H05, H05);
                    __half2 tg = tanh2(zg);
                    __half2 cc = __hfma2(sf, c2[m][uh][pr], __hmul2(si, tg));
                    c2[m][uh][pr] = cc;
                    __half2 h2 = __hmul2(so, tanh2(cc));
                    const int u0 = 16 * wv + uh * 8 + 2 * r4;
                    const int row = T * 32 + rl;
                    *(__half2*)(hn + row * WSTR + u0) = h2;
                    if (t == L_DIM - 1) {
                        float* ob = (is_q ? g_q : g_k) + (size_t)head * NSEQ * DH;
                        int n1 = n0 + row;
                        if (n1 < NSEQ) {
                            float2 f = __half22float2(h2);
                            ob[(size_t)n1 * DH + u0]     = f.x;
                            ob[(size_t)n1 * DH + u0 + 1] = f.y;
                        }
                    }
                }
            }

        // x ring for t+1 (team slice); prefetch x_{t+2}
        if (wv == 0 && t < L_DIM - 1) {
            xs[((t + 1) & 1) * MSEQ + T * 32 + lane] = xnext;
            if (t + 2 < L_DIM) {
                int n = n0 + T * 32 + lane;
                xnext = (n < NSEQ) ? g_xT[(t + 2) * NSEQ + n] : 0.f;
            }
        }
        team_bar(T);   // per-team barrier: teams free-run relative to each other
    }
}

// ---------------- attention: scores + leaky + mask + softmax + AV + leaky ----
__global__ __launch_bounds__(256, 2) void attn_kernel(const float* __restrict__ graph,
                                                      float* __restrict__ out) {
    extern __shared__ char smem_raw[];
    float* qs = (float*)smem_raw;     // [32][129]
    float* sc = qs + 32 * 129;        // [32][336]
    float* kv = sc + 32 * 336;        // [32][193]

    const int tid = threadIdx.x;
    const int h = blockIdx.z, b = blockIdx.y;
    const int s0 = blockIdx.x * 32;
    const int nrows = min(32, S_DIM - s0);
    const int w = tid >> 5, lane = tid & 31;

    for (int i = tid; i < nrows * 128; i += 256) {
        int r = i >> 7, d = i & 127;
        qs[r * 129 + d] = g_q[((size_t)h * NSEQ + (size_t)b * S_DIM + s0 + r) * 128 + d];
    }
    __syncthreads();

    for (int tk = 0; tk < S_DIM; tk += 32) {
        int tw = min(32, S_DIM - tk);
        for (int i = tid; i < tw * 128; i += 256) {
            int r = i >> 7, d = i & 127;
            kv[r * 129 + d] = g_k[((size_t)h * NSEQ + (size_t)b * S_DIM + tk + r) * 128 + d];
        }
        __syncthreads();
        int si = lane;
        int tl0 = w * 4;
        if (si < nrows && tl0 < tw) {
            float a0 = 0, a1 = 0, a2 = 0, a3 = 0;
            const float* qrow = qs + si * 129;
            const float* k0 = kv + tl0 * 129;
#pragma unroll 4
            for (int d = 0; d < 128; d++) {
                float qv = qrow[d];
                a0 = fmaf(qv, k0[d], a0);
                a1 = fmaf(qv, k0[129 + d], a1);
                a2 = fmaf(qv, k0[258 + d], a2);
                a3 = fmaf(qv, k0[387 + d], a3);
            }
            float av[4] = {a0, a1, a2, a3};
#pragma unroll
            for (int j = 0; j < 4; j++) {
                int t = tk + tl0 + j;
                if (t < S_DIM) {
                    float v = av[j] * 0.08838834764831845f;  // 1/sqrt(128)
                    v = (v >= 0.f) ? v : 0.2f * v;           // leaky
                    float gval = graph[(size_t)t * S_DIM + (s0 + si)];
                    if (s0 + si == t) gval += 1.f;
                    if (gval == 0.f) v += NEG_F;             // mask
                    sc[si * 336 + t] = v;
                }
            }
        }
        __syncthreads();
    }

    for (int si = w; si < nrows; si += 8) {
        float* row = sc + si * 336;
        float m = -3.0e38f;
        for (int j = lane; j < S_DIM; j += 32) m = fmaxf(m, row[j]);
#pragma unroll
        for (int o = 16; o; o >>= 1) m = fmaxf(m, __shfl_xor_sync(0xffffffffu, m, o));
        float ssum = 0.f;
        for (int j = lane; j < S_DIM; j += 32) {
            float e = __expf(row[j] - m);
            row[j] = e;
            ssum += e;
        }
#pragma unroll
        for (int o = 16; o; o >>= 1) ssum += __shfl_xor_sync(0xffffffffu, ssum, o);
        float inv = 1.0f / ssum;
        for (int j = lane; j < S_DIM; j += 32) row[j] *= inv;
    }
    __syncthreads();

    float acc[24];
#pragma unroll
    for (int j = 0; j < 24; j++) acc[j] = 0.f;
    const int si2 = tid >> 3;
    const int lq = tid & 7;
    for (int tk = 0; tk < S_DIM; tk += 32) {
        int tw = min(32, S_DIM - tk);
        for (int i = tid; i < tw * 192; i += 256) {
            int r = i / 192, l = i - r * 192;
            kv[r * 193 + l] = g_v[((size_t)h * NSEQ + (size_t)b * S_DIM + tk + r) * 192 + l];
        }
        __syncthreads();
        if (si2 < nrows) {
            for (int t = 0; t < tw; t++) {
                float a = sc[si2 * 336 + tk + t];
                const float* vrow = kv + t * 193 + lq;
#pragma unroll
                for (int j = 0; j < 24; j++) acc[j] = fmaf(a, vrow[8 * j], acc[j]);
            }
        }
        __syncthreads();
    }
    if (si2 < nrows) {
        size_t base = ((size_t)(b * S_DIM + s0 + si2) * 192) * 8 + h;
#pragma unroll
        for (int j = 0; j < 24; j++) {
            float v = acc[j];
            v = (v >= 0.f) ? v : 0.2f * v;  // final leaky
            out[base + (size_t)(lq + 8 * j) * 8] = v;
        }
    }
}

extern "C" void kernel_launch(void* const* d_in, const int* in_sizes, int n_in,
                              void* d_out, int out_size) {
    const float* x     = (const float*)d_in[0];
    const float* graph = (const float*)d_in[1];
    const float* qWih  = (const float*)d_in[2];
    const float* qWhh  = (const float*)d_in[3];
    const float* qbih  = (const float*)d_in[4];
    const float* qbhh  = (const float*)d_in[5];
    const float* kWih  = (const float*)d_in[6];
    const float* kWhh  = (const float*)d_in[7];
    const float* kbih  = (const float*)d_in[8];
    const float* kbhh  = (const float*)d_in[9];
    const float* vWih  = (const float*)d_in[10];
    const float* vWhh  = (const float*)d_in[11];
    const float* vbih  = (const float*)d_in[12];
    const float* vbhh  = (const float*)d_in[13];
    float* out = (float*)d_out;

    cudaFuncSetAttribute(qk_lstm_mma, cudaFuncAttributeMaxDynamicSharedMemorySize, QK_SMEM);
    cudaFuncSetAttribute(attn_kernel, cudaFuncAttributeMaxDynamicSharedMemorySize, ATTN_SMEM);

    dummy_kernel<<<1, 32>>>();
    xT_kernel<<<(NSEQ * L_DIM + 255) / 256, 256>>>(x);
    v_lstm_kernel<<<dim3((NSEQ + 255) / 256, NH), 256>>>(vWih, vWhh, vbih, vbhh);
    qk_lstm_mma<<<dim3(NBLK, 16), 512, QK_SMEM>>>(qWih, qWhh, qbih, qbhh,
                                                  kWih, kWhh, kbih, kbhh);
    attn_kernel<<<dim3((S_DIM + 31) / 32, B_DIM, NH), 256, ATTN_SMEM>>>(graph, out);
}

// round 17
// speedup vs baseline: 1.3884x; 1.0654x over previous
#include <cuda_runtime.h>
#include <cuda_fp16.h>
#include <math.h>

#define B_DIM 32
#define S_DIM 325
#define L_DIM 192
#define NSEQ (B_DIM * S_DIM)   // 10400
#define DH 128
#define NH 8
#define NEG_F (-1000000000.0f)

// ---- qk fp16 HMMA kernel geometry ----
#define MSEQ 64                          // sequences per block (2 teams x 32)
#define WSTR 136                         // half stride: 128 + 8 pad
#define NBLK ((NSEQ + MSEQ - 1) / MSEQ)  // 163
#define SM_W_BYTES (512 * WSTR * 2)      // 139264
#define SM_H_BYTES (MSEQ * WSTR * 2)     // 17408
#define SM_HA SM_W_BYTES
#define SM_HB (SM_W_BYTES + SM_H_BYTES)
#define SM_XS (SM_W_BYTES + 2 * SM_H_BYTES)
#define QK_SMEM (SM_XS + 2 * MSEQ * 4)   // 174592 bytes -> 1 block/SM

// one-time skew for team 1 (cycles); ~half of the measured 6400-cyc step
#define SKEW_CYC 3200ull

#define ATTN_SMEM ((32*129 + 32*336 + 32*193) * 4) // 84224 bytes

// ---- scratch (static device arrays; no allocation allowed) ----
__device__ float g_xT[L_DIM * NSEQ];            // x transposed [t][n]
__device__ float g_q[NH * NSEQ * DH];           // [h][n][d]
__device__ float g_k[NH * NSEQ * DH];           // [h][n][d]
__device__ float g_v[NH * NSEQ * L_DIM];        // [h][n][l]

__device__ __forceinline__ float sigf(float x) { return 1.0f / (1.0f + __expf(-x)); }
__device__ __forceinline__ float tanh_fast(float x) { return 2.0f / (1.0f + __expf(-2.0f * x)) - 1.0f; }

__device__ __forceinline__ __half2 tanh2(__half2 x) {
    unsigned y, xi = *(unsigned*)&x;
    asm("tanh.approx.f16x2 %0, %1;" : "=r"(y) : "r"(xi));
    return *(__half2*)&y;
}

__device__ __forceinline__ void ldsm4(unsigned& r0, unsigned& r1, unsigned& r2, unsigned& r3,
                                      const void* p) {
    unsigned a = (unsigned)__cvta_generic_to_shared(p);
    asm volatile("ldmatrix.sync.aligned.m8n8.x4.shared.b16 {%0,%1,%2,%3}, [%4];"
                 : "=r"(r0), "=r"(r1), "=r"(r2), "=r"(r3) : "r"(a));
}
// f16-accumulator HMMA: D,C are 2x f16x2 regs
__device__ __forceinline__ void mma16816h(unsigned* d, const unsigned* a, unsigned b0, unsigned b1) {
    asm volatile("mma.sync.aligned.m16n8k16.row.col.f16.f16.f16.f16 "
                 "{%0,%1}, {%2,%3,%4,%5}, {%6,%7}, {%0,%1};"
                 : "+r"(d[0]), "+r"(d[1])
                 : "r"(a[0]), "r"(a[1]), "r"(a[2]), "r"(a[3]), "r"(b0), "r"(b1));
}
__device__ __forceinline__ void team_bar(int T) {
    asm volatile("bar.sync %0, 256;" :: "r"(1 + T) : "memory");
}

// ---------------- dummy (keeps ncu capture slot on qk kernel) ----------------
__global__ void dummy_kernel() {}

// ---------------- x transpose: [n][t] -> [t][n] ----------------
__global__ void xT_kernel(const float* __restrict__ x) {
    int i = blockIdx.x * 256 + threadIdx.x;
    if (i < NSEQ * L_DIM) {
        int n = i / L_DIM, t = i - n * L_DIM;
        g_xT[t * NSEQ + n] = x[i];
    }
}

// ---------------- v LSTM (hidden size 1) ----------------
__global__ void v_lstm_kernel(const float* __restrict__ Wih, const float* __restrict__ Whh,
                              const float* __restrict__ bih, const float* __restrict__ bhh) {
    int n = blockIdx.x * 256 + threadIdx.x;
    int h = blockIdx.y;
    if (n >= NSEQ) return;
    float wi[4], wh[4], bb[4];
#pragma unroll
    for (int g = 0; g < 4; g++) {
        wi[g] = Wih[h * 4 + g];
        wh[g] = Whh[h * 4 + g];
        bb[g] = bih[h * 4 + g] + bhh[h * 4 + g];
    }
    float hv = 0.f, c = 0.f;
    float4 buf;
    float* vout = g_v + ((size_t)h * NSEQ + n) * L_DIM;
    for (int t = 0; t < L_DIM; t++) {
        float xv = g_xT[t * NSEQ + n];
        float zi = xv * wi[0] + hv * wh[0] + bb[0];
        float zf = xv * wi[1] + hv * wh[1] + bb[1];
        float zg = xv * wi[2] + hv * wh[2] + bb[2];
        float zo = xv * wi[3] + hv * wh[3] + bb[3];
        c = sigf(zf) * c + sigf(zi) * tanh_fast(zg);
        hv = sigf(zo) * tanh_fast(c);
        ((float*)&buf)[t & 3] = hv;
        if ((t & 3) == 3) *(float4*)(vout + (t - 3)) = buf;
    }
}

// ---------------- q/k LSTM on fp16 tensor cores (m16n8k16, f16 acc) ----------
// grid (163, 16). 512 threads = 16 warps. warp = T*8 + wv:
//   T  = M-team (seqs [32T, 32T+32) of the block's 64)
//   wv = N-chunk (permuted gate cols [64wv, 64wv+64) = units [16wv,16wv+16) x 4 gates)
// f16 accumulators; bias + x*Wih folded into C-operand init. Teams are fully
// data-independent and sync on their OWN named barrier. Team 1 takes a one-time
// ~half-step delay before the loop so the teams run in anti-phase: one team's
// MUFU/LDSM epilogue overlaps the other team's HMMA phase on each SMSP.
__global__ __launch_bounds__(512, 1) void qk_lstm_mma(
    const float* __restrict__ qWih, const float* __restrict__ qWhh,
    const float* __restrict__ qbih, const float* __restrict__ qbhh,
    const float* __restrict__ kWih, const float* __restrict__ kWhh,
    const float* __restrict__ kbih, const float* __restrict__ kbhh) {
    extern __shared__ char sm[];
    __half* ws = (__half*)sm;                        // permuted W fp16 [512][WSTR]
    __half* hbufA = (__half*)(sm + SM_HA);           // h [64][WSTR] fp16
    __half* hbufB = (__half*)(sm + SM_HB);
    float* xs = (float*)(sm + SM_XS);                // x ring [2][64]

    const int tid = threadIdx.x;
    const int warp = tid >> 5, lane = tid & 31;
    const int T = warp >> 3, wv = warp & 7;
    const int q4 = lane >> 2, r4 = lane & 3;
    const int grp = lane >> 3, ro = lane & 7;
    const int p = blockIdx.y, head = p & 7;
    const bool is_q = p < 8;
    const int n0 = blockIdx.x * MSEQ;

    const float* Wih = (is_q ? qWih : kWih) + head * 512;
    const float* Whh = (is_q ? qWhh : kWhh) + (size_t)head * 512 * 128;
    const float* bih = (is_q ? qbih : kbih) + head * 512;
    const float* bhh = (is_q ? qbhh : kbhh) + head * 512;

    // zero all smem (pad tails and h buffers must start 0)
    for (int i = tid; i < QK_SMEM / 4; i += 512) ((unsigned*)sm)[i] = 0u;
    __syncthreads();

    // stage permuted recurrent weights fp16
    for (int i = tid; i < 512 * 64; i += 512) {
        int row = i >> 6, kp = i & 63;
        int g = row >> 7, j = row & 127;
        int pcol = (j >> 4) * 64 + (g * 2 + ((j >> 3) & 1)) * 8 + (j & 7);
        *(__half2*)(ws + pcol * WSTR + 2 * kp) =
            __floats2half2_rn(Whh[row * 128 + 2 * kp], Whh[row * 128 + 2 * kp + 1]);
    }
    // prime x for t=0
    if (tid < MSEQ) {
        int n = n0 + tid;
        xs[tid] = (n < NSEQ) ? g_xT[n] : 0.f;
    }

    // per-thread input weights / biases in half2 (nt = gate*2 + uh; covers the
    // thread's column pair = units 16wv + uh*8 + 2r4, +1)
    __half2 wih2[8], b2[8];
#pragma unroll
    for (int nt = 0; nt < 8; nt++) {
        int g = nt >> 1, uh = nt & 1;
        int u = 16 * wv + uh * 8 + 2 * r4;
        int r0 = g * 128 + u;
        wih2[nt] = __floats2half2_rn(Wih[r0], Wih[r0 + 1]);
        b2[nt] = __floats2half2_rn(bih[r0] + bhh[r0], bih[r0 + 1] + bhh[r0 + 1]);
    }

    __half2 c2[2][2][2];  // [m][uh][pr]
#pragma unroll
    for (int m = 0; m < 2; m++)
#pragma unroll
        for (int uh = 0; uh < 2; uh++)
#pragma unroll
            for (int pr = 0; pr < 2; pr++) c2[m][uh][pr] = __floats2half2_rn(0.f, 0.f);

    // ldmatrix lane address components (half-element offsets)
    const int a_row = (grp & 1) * 8 + ro, a_k = (grp >> 1) * 8;
    const int b_row = (grp >> 1) * 8 + ro, b_k = (grp & 1) * 8;
    const int wN0 = wv * 64;
    const __half2 H05 = __floats2half2_rn(0.5f, 0.5f);

    // rolling x prefetch (wv==0 warps, one per team): x_{t+1} during step t
    float xnext = 0.f;
    if (wv == 0) {
        int n = n0 + T * 32 + lane;
        xnext = (n < NSEQ) ? g_xT[NSEQ + n] : 0.f;   // x_1
    }

    __syncthreads();   // W staged by whole block: last block-wide barrier

    // anti-phase skew: team 1 starts ~half a step late (one-time, persists)
    if (T == 1) {
        unsigned long long s0 = clock64();
        while (clock64() - s0 < SKEW_CYC) {}
    }

    for (int t = 0; t < L_DIM; t++) {
        const __half* hc = (t & 1) ? hbufB : hbufA;
        __half* hn = (t & 1) ? hbufA : hbufB;

        // C-operand init: z = b + x * Wih (f16x2). reg pr covers row q4+8*pr.
        unsigned acc[2][8][2];
        const float* xrow = xs + (t & 1) * MSEQ + T * 32;
#pragma unroll
        for (int m = 0; m < 2; m++) {
            const __half2 x0 = __float2half2_rn(xrow[m * 16 + q4]);
            const __half2 x1 = __float2half2_rn(xrow[m * 16 + q4 + 8]);
#pragma unroll
            for (int nt = 0; nt < 8; nt++) {
                __half2 v0 = __hfma2(x0, wih2[nt], b2[nt]);
                __half2 v1 = __hfma2(x1, wih2[nt], b2[nt]);
                acc[m][nt][0] = *(unsigned*)&v0;
                acc[m][nt][1] = *(unsigned*)&v1;
            }
        }

        // Z += H @ W^T over K=128 in 8 k16 chunks (team's own 32 rows)
#pragma unroll
        for (int kt = 0; kt < 8; kt++) {
            const int koff = kt * 16;
            unsigned a[2][4], b[4][4];
#pragma unroll
            for (int m = 0; m < 2; m++)
                ldsm4(a[m][0], a[m][1], a[m][2], a[m][3],
                      hc + (T * 32 + m * 16 + a_row) * WSTR + koff + a_k);
#pragma unroll
            for (int jj = 0; jj < 4; jj++)
                ldsm4(b[jj][0], b[jj][1], b[jj][2], b[jj][3],
                      ws + (wN0 + jj * 16 + b_row) * WSTR + koff + b_k);
#pragma unroll
            for (int m = 0; m < 2; m++)
#pragma unroll
                for (int jj = 0; jj < 4; jj++) {
                    mma16816h(acc[m][2 * jj],     a[m], b[jj][0], b[jj][1]);
                    mma16816h(acc[m][2 * jj + 1], a[m], b[jj][2], b[jj][3]);
                }
        }

        // epilogue: acc IS z (f16x2). LSTM nonlinearity, h -> fp16 SMEM
#pragma unroll
        for (int m = 0; m < 2; m++)
#pragma unroll
            for (int pr = 0; pr < 2; pr++) {
                const int rl = m * 16 + q4 + pr * 8;   // row in team
#pragma unroll
                for (int uh = 0; uh < 2; uh++) {
                    __half2 zi = *(__half2*)&acc[m][0 + uh][pr];
                    __half2 zf = *(__half2*)&acc[m][2 + uh][pr];
                    __half2 zg = *(__half2*)&acc[m][4 + uh][pr];
                    __half2 zo = *(__half2*)&acc[m][6 + uh][pr];
                    __half2 si = __hfma2(tanh2(__hmul2(zi, H05)), H05, H05);
                    __half2 sf = __hfma2(tanh2(__hmul2(zf, H05)), H05, H05);
                    __half2 so = __hfma2(tanh2(__hmul2(zo, H05)), H05, H05);
                    __half2 tg = tanh2(zg);
                    __half2 cc = __hfma2(sf, c2[m][uh][pr], __hmul2(si, tg));
                    c2[m][uh][pr] = cc;
                    __half2 h2 = __hmul2(so, tanh2(cc));
                    const int u0 = 16 * wv + uh * 8 + 2 * r4;
                    const int row = T * 32 + rl;
                    *(__half2*)(hn + row * WSTR + u0) = h2;
                    if (t == L_DIM - 1) {
                        float* ob = (is_q ? g_q : g_k) + (size_t)head * NSEQ * DH;
                        int n1 = n0 + row;
                        if (n1 < NSEQ) {
                            float2 f = __half22float2(h2);
                            ob[(size_t)n1 * DH + u0]     = f.x;
                            ob[(size_t)n1 * DH + u0 + 1] = f.y;
                        }
                    }
                }
            }

        // x ring for t+1 (team slice); prefetch x_{t+2}
        if (wv == 0 && t < L_DIM - 1) {
            xs[((t + 1) & 1) * MSEQ + T * 32 + lane] = xnext;
            if (t + 2 < L_DIM) {
                int n = n0 + T * 32 + lane;
                xnext = (n < NSEQ) ? g_xT[(t + 2) * NSEQ + n] : 0.f;
            }
        }
        team_bar(T);   // per-team barrier: teams free-run relative to each other
    }
}

// ---------------- attention: scores + leaky + mask + softmax + AV + leaky ----
__global__ __launch_bounds__(256, 2) void attn_kernel(const float* __restrict__ graph,
                                                      float* __restrict__ out) {
    extern __shared__ char smem_raw[];
    float* qs = (float*)smem_raw;     // [32][129]
    float* sc = qs + 32 * 129;        // [32][336]
    float* kv = sc + 32 * 336;        // [32][193]

    const int tid = threadIdx.x;
    const int h = blockIdx.z, b = blockIdx.y;
    const int s0 = blockIdx.x * 32;
    const int nrows = min(32, S_DIM - s0);
    const int w = tid >> 5, lane = tid & 31;

    for (int i = tid; i < nrows * 128; i += 256) {
        int r = i >> 7, d = i & 127;
        qs[r * 129 + d] = g_q[((size_t)h * NSEQ + (size_t)b * S_DIM + s0 + r) * 128 + d];
    }
    __syncthreads();

    for (int tk = 0; tk < S_DIM; tk += 32) {
        int tw = min(32, S_DIM - tk);
        for (int i = tid; i < tw * 128; i += 256) {
            int r = i >> 7, d = i & 127;
            kv[r * 129 + d] = g_k[((size_t)h * NSEQ + (size_t)b * S_DIM + tk + r) * 128 + d];
        }
        __syncthreads();
        int si = lane;
        int tl0 = w * 4;
        if (si < nrows && tl0 < tw) {
            float a0 = 0, a1 = 0, a2 = 0, a3 = 0;
            const float* qrow = qs + si * 129;
            const float* k0 = kv + tl0 * 129;
#pragma unroll 4
            for (int d = 0; d < 128; d++) {
                float qv = qrow[d];
                a0 = fmaf(qv, k0[d], a0);
                a1 = fmaf(qv, k0[129 + d], a1);
                a2 = fmaf(qv, k0[258 + d], a2);
                a3 = fmaf(qv, k0[387 + d], a3);
            }
            float av[4] = {a0, a1, a2, a3};
#pragma unroll
            for (int j = 0; j < 4; j++) {
                int t = tk + tl0 + j;
                if (t < S_DIM) {
                    float v = av[j] * 0.08838834764831845f;  // 1/sqrt(128)
                    v = (v >= 0.f) ? v : 0.2f * v;           // leaky
                    float gval = graph[(size_t)t * S_DIM + (s0 + si)];
                    if (s0 + si == t) gval += 1.f;
                    if (gval == 0.f) v += NEG_F;             // mask
                    sc[si * 336 + t] = v;
                }
            }
        }
        __syncthreads();
    }

    for (int si = w; si < nrows; si += 8) {
        float* row = sc + si * 336;
        float m = -3.0e38f;
        for (int j = lane; j < S_DIM; j += 32) m = fmaxf(m, row[j]);
#pragma unroll
        for (int o = 16; o; o >>= 1) m = fmaxf(m, __shfl_xor_sync(0xffffffffu, m, o));
        float ssum = 0.f;
        for (int j = lane; j < S_DIM; j += 32) {
            float e = __expf(row[j] - m);
            row[j] = e;
            ssum += e;
        }
#pragma unroll
        for (int o = 16; o; o >>= 1) ssum += __shfl_xor_sync(0xffffffffu, ssum, o);
        float inv = 1.0f / ssum;
        for (int j = lane; j < S_DIM; j += 32) row[j] *= inv;
    }
    __syncthreads();

    float acc[24];
#pragma unroll
    for (int j = 0; j < 24; j++) acc[j] = 0.f;
    const int si2 = tid >> 3;
    const int lq = tid & 7;
    for (int tk = 0; tk < S_DIM; tk += 32) {
        int tw = min(32, S_DIM - tk);
        for (int i = tid; i < tw * 192; i += 256) {
            int r = i / 192, l = i - r * 192;
            kv[r * 193 + l] = g_v[((size_t)h * NSEQ + (size_t)b * S_DIM + tk + r) * 192 + l];
        }
        __syncthreads();
        if (si2 < nrows) {
            for (int t = 0; t < tw; t++) {
                float a = sc[si2 * 336 + tk + t];
                const float* vrow = kv + t * 193 + lq;
#pragma unroll
                for (int j = 0; j < 24; j++) acc[j] = fmaf(a, vrow[8 * j], acc[j]);
            }
        }
        __syncthreads();
    }
    if (si2 < nrows) {
        size_t base = ((size_t)(b * S_DIM + s0 + si2) * 192) * 8 + h;
#pragma unroll
        for (int j = 0; j < 24; j++) {
            float v = acc[j];
            v = (v >= 0.f) ? v : 0.2f * v;  // final leaky
            out[base + (size_t)(lq + 8 * j) * 8] = v;
        }
    }
}

extern "C" void kernel_launch(void* const* d_in, const int* in_sizes, int n_in,
                              void* d_out, int out_size) {
    const float* x     = (const float*)d_in[0];
    const float* graph = (const float*)d_in[1];
    const float* qWih  = (const float*)d_in[2];
    const float* qWhh  = (const float*)d_in[3];
    const float* qbih  = (const float*)d_in[4];
    const float* qbhh  = (const float*)d_in[5];
    const float* kWih  = (const float*)d_in[6];
    const float* kWhh  = (const float*)d_in[7];
    const float* kbih  = (const float*)d_in[8];
    const float* kbhh  = (const float*)d_in[9];
    const float* vWih  = (const float*)d_in[10];
    const float* vWhh  = (const float*)d_in[11];
    const float* vbih  = (const float*)d_in[12];
    const float* vbhh  = (const float*)d_in[13];
    float* out = (float*)d_out;

    cudaFuncSetAttribute(qk_lstm_mma, cudaFuncAttributeMaxDynamicSharedMemorySize, QK_SMEM);
    cudaFuncSetAttribute(attn_kernel, cudaFuncAttributeMaxDynamicSharedMemorySize, ATTN_SMEM);

    dummy_kernel<<<1, 32>>>();
    xT_kernel<<<(NSEQ * L_DIM + 255) / 256, 256>>>(x);
    v_lstm_kernel<<<dim3((NSEQ + 255) / 256, NH), 256>>>(vWih, vWhh, vbih, vbhh);
    qk_lstm_mma<<<dim3(NBLK, 16), 512, QK_SMEM>>>(qWih, qWhh, qbih, qbhh,
                                                  kWih, kWhh, kbih, kbhh);
    attn_kernel<<<dim3((S_DIM + 31) / 32, B_DIM, NH), 256, ATTN_SMEM>>>(graph, out);
}